// round 11
// baseline (speedup 1.0000x reference)
#include <cuda_runtime.h>

#define BATCH 128
#define DIM   65536
#define NELEM (BATCH * DIM)

typedef unsigned long long u64;

// ---- scratch / precomputed tables (static device memory; no runtime allocs) ----
static __device__ float2 g_bufA[NELEM];          // 64 MB
static __device__ float2 g_bufB[NELEM];          // 64 MB
static __device__ float  g_partials[BATCH * 16];
static __device__ float2 g_cs[3][16];            // (cos(th/2), sin(th/2)) per layer/wire
static __device__ float2 g_Dhi[3][256];          // diagonal phase, wires 0..7  (bits 15..8)
static __device__ float2 g_Dlo[3][256];          // diagonal phase, wires 8..15 (bits 7..0)
static __device__ float  g_Ghi[256];             // head-weighted Z signs, wires 0..7
static __device__ float  g_Glo[256];             // head-weighted Z signs, wires 8..15

// ---- packed f32x2 helpers (FFMA2 path: PTX-only) ----
__device__ __forceinline__ u64 pk(float x, float y) {
    u64 r; asm("mov.b64 %0,{%1,%2};" : "=l"(r) : "f"(x), "f"(y)); return r;
}
__device__ __forceinline__ void upk(u64 a, float& x, float& y) {
    asm("mov.b64 {%0,%1},%2;" : "=f"(x), "=f"(y) : "l"(a));
}
__device__ __forceinline__ u64 fma2(u64 a, u64 b, u64 c) {
    u64 r; asm("fma.rn.f32x2 %0,%1,%2,%3;" : "=l"(r) : "l"(a), "l"(b), "l"(c)); return r;
}
__device__ __forceinline__ u64 mul2(u64 a, u64 b) {
    u64 r; asm("mul.rn.f32x2 %0,%1,%2;" : "=l"(r) : "l"(a), "l"(b)); return r;
}

// swizzles
__device__ __forceinline__ int swz(int i) {      // for k_low_real patterns
    return i ^ ((i >> 4) & 15) ^ (((i >> 8) & 1) << 4);
}
__device__ __forceinline__ int sw2(int i) {      // for fuse-kernel staged tile
    return i ^ ((i >> 4) & 15);
}

// Composite CNOT-ring permutation (forward basis map): out[M(a)] = psi[a].
__device__ __forceinline__ int permM(int a) {
    int t = a;
    t ^= t >> 8; t ^= t >> 4; t ^= t >> 2; t ^= t >> 1;
    return t ^ ((t & 1) << 15);
}
__device__ __forceinline__ int sfx4(int m) { m ^= m >> 2; m ^= m >> 1; return m & 15; }

// 4 RY butterflies; local bit q of j <-> wire (wtop - q).
__device__ __forceinline__ void bfly4_real(float v[16], int layer, int wtop) {
#pragma unroll
    for (int q = 0; q < 4; q++) {
        float2 cs = g_cs[layer][wtop - q];
        float c = cs.x, s = cs.y;
#pragma unroll
        for (int j = 0; j < 16; j++) {
            if (!(j & (1 << q))) {
                int j1 = j | (1 << q);
                float x0 = v[j], x1 = v[j1];
                v[j]  = c * x0 - s * x1;
                v[j1] = s * x0 + c * x1;
            }
        }
    }
}

__device__ __forceinline__ void bfly4_pk(u64 v[16], int layer, int wtop) {
#pragma unroll
    for (int q = 0; q < 4; q++) {
        float2 cs = g_cs[layer][wtop - q];
        u64 cc = pk(cs.x, cs.x), sp = pk(cs.y, cs.y), sn = pk(-cs.y, -cs.y);
#pragma unroll
        for (int j = 0; j < 16; j++) {
            if (!(j & (1 << q))) {
                int j1 = j | (1 << q);
                u64 x0 = v[j], x1 = v[j1];
                v[j]  = fma2(sn, x1, mul2(cc, x0));
                v[j1] = fma2(sp, x0, mul2(cc, x1));
            }
        }
    }
}

// ---- precompute tables ----
__global__ void k_pre(const float* __restrict__ params, const float* __restrict__ head_w) {
    int t = threadIdx.x;  // 256
    if (t < 48) {
        int d = t >> 4, w = t & 15;
        float th = params[(d * 16 + w) * 2 + 0] * 0.5f;
        g_cs[d][w] = make_float2(cosf(th), sinf(th));
    }
    for (int d = 0; d < 3; d++) {
        float ah = 0.f, al = 0.f;
        for (int w = 0; w < 8; w++) {
            float ph = params[(d * 16 + w) * 2 + 1] * 0.5f;
            ah += ((t >> (7 - w)) & 1) ? -ph : ph;
        }
        for (int w = 8; w < 16; w++) {
            float ph = params[(d * 16 + w) * 2 + 1] * 0.5f;
            al += ((t >> (15 - w)) & 1) ? -ph : ph;
        }
        g_Dhi[d][t] = make_float2(cosf(ah), -sinf(ah));
        g_Dlo[d][t] = make_float2(cosf(al), -sinf(al));
    }
    float gh = 0.f, gl = 0.f;
    for (int w = 0; w < 8; w++)  gh += ((t >> (7 - w)) & 1)  ? -head_w[w] : head_w[w];
    for (int w = 8; w < 16; w++) gl += ((t >> (15 - w)) & 1) ? -head_w[w] : head_w[w];
    g_Ghi[t] = gh;
    g_Glo[t] = gl;
}

// All heavy kernels take a block offset `boff` (in blocks) so the batch can be
// processed in L2-resident chunks: per chunk the live set (bufA+bufB slices)
// fits in the 126MB L2, so intermediate passes run at LTS speed, not DRAM.

// ---- K1: layer-0 real RY on wires 4..15 (bits 11..0), contiguous tile ----
__global__ void __launch_bounds__(256) k_low_real(const float* __restrict__ in, int boff) {
    __shared__ float tile[4096];
    float* out = (float*)(void*)g_bufA;
    int base = (blockIdx.x + boff) << 12;
    int t = threadIdx.x;
    float v[16];
#pragma unroll
    for (int j = 0; j < 16; j++) v[j] = in[base + t + (j << 8)];
    bfly4_real(v, 0, 7);                       // bits 8..11 -> wires 7..4
#pragma unroll
    for (int j = 0; j < 16; j++) tile[swz(t | (j << 8))] = v[j];
    __syncthreads();
    {
        int b = (t & 15) | ((t >> 4) << 8);
#pragma unroll
        for (int j = 0; j < 16; j++) v[j] = tile[swz(b | (j << 4))];
        bfly4_real(v, 0, 11);                  // bits 4..7 -> wires 11..8
#pragma unroll
        for (int j = 0; j < 16; j++) tile[swz(b | (j << 4))] = v[j];
    }
    __syncthreads();
    {
        int b = t << 4;
#pragma unroll
        for (int j = 0; j < 16; j++) v[j] = tile[swz(b | j)];
        bfly4_real(v, 0, 15);                  // bits 0..3 -> wires 15..12
        float4* o = (float4*)(out + base + b);
#pragma unroll
        for (int m = 0; m < 4; m++)
            o[m] = make_float4(v[4 * m], v[4 * m + 1], v[4 * m + 2], v[4 * m + 3]);
    }
}

// ---- K2 (k_fuse0): L0 wires 0..3 (real) + D0 + P0 scatter + L1 wires 8..15 in-tile.
//      bufA(real) -> bufB(complex). g_Dhi values are block-uniform -> staged in smem. ----
__global__ void __launch_bounds__(256) k_fuse0(int boff) {
    __shared__ u64 st[4096];
    __shared__ float2 sDh[16];
    const float* in = (const float*)(const void*)g_bufA;
    u64* out = (u64*)(void*)g_bufB;
    int bid = blockIdx.x + boff;
    int s = bid >> 4, mid = bid & 15;
    int lo = threadIdx.x;
    int sbase = s << 16;
    int abase = (mid << 8) | lo;
    if (lo < 16) sDh[lo] = g_Dhi[0][(lo << 4) | mid];   // dh for h = lo
    float v[16];
#pragma unroll
    for (int h = 0; h < 16; h++) v[h] = in[sbase | (h << 12) | abase];
    bfly4_real(v, 0, 3);                       // bits 12..15 -> wires 3..0
    float2 dlo = g_Dlo[0][lo];
    __syncthreads();                           // sDh visible; st untouched yet
#pragma unroll
    for (int h = 0; h < 16; h++) {
        int a = (h << 12) | abase;
        int dest = permM(a);
        float2 dh = sDh[h];
        float dcr = dh.x * dlo.x - dh.y * dlo.y;
        float dci = dh.x * dlo.y + dh.y * dlo.x;
        st[sw2(((dest >> 12) << 8) | (dest & 255))] = mul2(pk(v[h], v[h]), pk(dcr, dci));
    }
    __syncthreads();
    // stage S: L1 wires 8..11 (dest bits 7..4); thread = (row k, m)
    {
        int k = threadIdx.x >> 4, m = threadIdx.x & 15;
        u64 w[16];
#pragma unroll
        for (int j = 0; j < 16; j++) w[j] = st[sw2((k << 8) | (j << 4) | m)];
        bfly4_pk(w, 1, 11);
#pragma unroll
        for (int j = 0; j < 16; j++) st[sw2((k << 8) | (j << 4) | m)] = w[j];
    }
    __syncthreads();
    // stage T: L1 wires 12..15 (dest bits 3..0); ends in regs -> coalesced 2KB rows.
    {
        int k = threadIdx.x >> 4, gg = threadIdx.x & 15;
        u64 w[16];
#pragma unroll
        for (int j = 0; j < 16; j++) w[j] = st[sw2((k << 8) | (gg << 4) | j)];
        bfly4_pk(w, 1, 15);
        int ms = sfx4(mid);
        int H = (k << 4) | (ms ^ ((k & 1) ? 15 : 0));      // dest bits 8..15
        ulonglong2* o = (ulonglong2*)(out + (sbase | (H << 8) | (gg << 4)));
#pragma unroll
        for (int m2 = 0; m2 < 8; m2++) {
            ulonglong2 p; p.x = w[2 * m2]; p.y = w[2 * m2 + 1];
            o[m2] = p;
        }
    }
}

// ---- K3 (k_mid4): L1 wires 4..7 (bits 11..8), pure-register, in-place on bufB ----
__global__ void __launch_bounds__(256, 5) k_mid4(int boff) {
    u64* buf = (u64*)(void*)g_bufB;
    int base = (blockIdx.x + boff) << 12;
    int t = threadIdx.x;
    u64 v[16];
#pragma unroll
    for (int j = 0; j < 16; j++) v[j] = buf[base + t + (j << 8)];
    bfly4_pk(v, 1, 7);                         // bits 8..11 -> wires 7..4
#pragma unroll
    for (int j = 0; j < 16; j++) buf[base + t + (j << 8)] = v[j];
}

// ---- K4 (k_fuse1): L1 wires 0..3 + D1 + P1 scatter + L2 wires 8..15 in-tile.
//      bufB -> bufA. ----
__global__ void __launch_bounds__(256) k_fuse1(int boff) {
    __shared__ u64 st[4096];
    __shared__ float2 sDh[16];
    const u64* in = (const u64*)(const void*)g_bufB;
    u64* out = (u64*)(void*)g_bufA;
    int bid = blockIdx.x + boff;
    int s = bid >> 4, mid = bid & 15;
    int lo = threadIdx.x;
    int sbase = s << 16;
    int abase = (mid << 8) | lo;
    if (lo < 16) sDh[lo] = g_Dhi[1][(lo << 4) | mid];
    u64 v[16];
#pragma unroll
    for (int h = 0; h < 16; h++) v[h] = in[sbase | (h << 12) | abase];
    bfly4_pk(v, 1, 3);                         // L1 wires 3..0
    float2 dlo = g_Dlo[1][lo];
    __syncthreads();
#pragma unroll
    for (int h = 0; h < 16; h++) {
        int a = (h << 12) | abase;
        int dest = permM(a);
        float2 dh = sDh[h];
        float dcr = dh.x * dlo.x - dh.y * dlo.y;
        float dci = dh.x * dlo.y + dh.y * dlo.x;
        float xr, xi; upk(v[h], xr, xi);
        u64 res = fma2(pk(xi, xi), pk(-dci, dcr), mul2(pk(xr, xr), pk(dcr, dci)));
        st[sw2(((dest >> 12) << 8) | (dest & 255))] = res;
    }
    __syncthreads();
    {
        int k = threadIdx.x >> 4, m = threadIdx.x & 15;
        u64 w[16];
#pragma unroll
        for (int j = 0; j < 16; j++) w[j] = st[sw2((k << 8) | (j << 4) | m)];
        bfly4_pk(w, 2, 11);                    // L2 wires 8..11
#pragma unroll
        for (int j = 0; j < 16; j++) st[sw2((k << 8) | (j << 4) | m)] = w[j];
    }
    __syncthreads();
    {
        int k = threadIdx.x >> 4, gg = threadIdx.x & 15;
        u64 w[16];
#pragma unroll
        for (int j = 0; j < 16; j++) w[j] = st[sw2((k << 8) | (gg << 4) | j)];
        bfly4_pk(w, 2, 15);                    // L2 wires 12..15
        int ms = sfx4(mid);
        int H = (k << 4) | (ms ^ ((k & 1) ? 15 : 0));
        ulonglong2* o = (ulonglong2*)(out + (sbase | (H << 8) | (gg << 4)));
#pragma unroll
        for (int m2 = 0; m2 < 8; m2++) {
            ulonglong2 p; p.x = w[2 * m2]; p.y = w[2 * m2 + 1];
            o[m2] = p;
        }
    }
}

// ---- K5 (k_tail): L2 wires 4..7 + wires 0..3 + fused measurement
//      (D2 skipped; P2 folded into sign lookup). bufA -> partials. ----
__global__ void __launch_bounds__(256) k_tail(int boff) {
    __shared__ u64 st[4096];
    __shared__ float sGhi[256], sGlo[256];
    const u64* in = (const u64*)(const void*)g_bufA;
    int bid = blockIdx.x + boff;
    int s = bid >> 4, lch = bid & 15;
    int loBase = lch << 4;
    int sbase = s << 16;
    int t = threadIdx.x;
    sGhi[t] = g_Ghi[t];
    sGlo[t] = g_Glo[t];
    // load tile: bits 8..15 full x 16 lo values
    {
        int l = t & 15, Ho = t >> 4;
#pragma unroll
        for (int i = 0; i < 16; i++) {
            int HH = Ho + (i << 4);
            st[(HH << 4) | l] = in[sbase | (HH << 8) | (loBase + l)];
        }
    }
    __syncthreads();
    // stage A: wires 4..7 (HH bits 0..3 = global bits 8..11)
    {
        int Hhi = t >> 4, l = t & 15;
        u64 w[16];
#pragma unroll
        for (int j = 0; j < 16; j++) w[j] = st[(Hhi << 8) | (j << 4) | l];
        bfly4_pk(w, 2, 7);
#pragma unroll
        for (int j = 0; j < 16; j++) st[(Hhi << 8) | (j << 4) | l] = w[j];
    }
    __syncthreads();
    // stage B: wires 0..3 (HH bits 4..7 = global bits 12..15) + measurement
    float acc = 0.f;
    {
        int Hlo = t >> 4, l = t & 15;
        u64 w[16];
#pragma unroll
        for (int j = 0; j < 16; j++) w[j] = st[(j << 8) | (Hlo << 4) | l];
        bfly4_pk(w, 2, 3);
        u64 accP = pk(0.f, 0.f);
#pragma unroll
        for (int j = 0; j < 16; j++) {
            int HH = (j << 4) | Hlo;
            int y = permM((HH << 8) | (loBase + l));
            float g = sGhi[(y >> 8) & 255] + sGlo[y & 255];
            accP = fma2(w[j], mul2(w[j], pk(g, g)), accP);
        }
        float ar, ai; upk(accP, ar, ai);
        acc = ar + ai;
    }
#pragma unroll
    for (int o = 16; o; o >>= 1) acc += __shfl_xor_sync(0xFFFFFFFFu, acc, o);
    __shared__ float red[8];
    if ((t & 31) == 0) red[t >> 5] = acc;
    __syncthreads();
    if (t == 0) {
        float tt = 0.f;
#pragma unroll
        for (int i = 0; i < 8; i++) tt += red[i];
        g_partials[bid] = tt;
    }
}

__global__ void k_final(const float* __restrict__ head_b, float* __restrict__ out) {
    int s = threadIdx.x;  // 128
    float a = 0.f;
#pragma unroll
    for (int m = 0; m < 16; m++) a += g_partials[(s << 4) + m];
    out[s] = head_b[0] + a;
}

extern "C" void kernel_launch(void* const* d_in, const int* in_sizes, int n_in,
                              void* d_out, int out_size) {
    const float* state  = (const float*)d_in[0];  // (128, 65536)
    const float* params = (const float*)d_in[1];  // (3, 16, 2)
    const float* head_w = (const float*)d_in[2];  // (1, 16)
    const float* head_b = (const float*)d_in[3];  // (1,)
    float* out = (float*)d_out;                   // (128,)
    (void)in_sizes; (void)n_in; (void)out_size;

    k_pre<<<1, 256>>>(params, head_w);

    // Process the batch in 2 L2-resident chunks of 64 states (live set ~64MB < 126MB L2).
    const int CHUNK_BLOCKS = 1024;   // 64 states x 16 blocks/state
    for (int c = 0; c < 2; c++) {
        int boff = c * CHUNK_BLOCKS;
        k_low_real<<<CHUNK_BLOCKS, 256>>>(state, boff); // L0 w4..15  (state -> bufA real)
        k_fuse0<<<CHUNK_BLOCKS, 256>>>(boff);  // L0 w0..3 +D0+P0+ L1 w8..15 (bufA -> bufB)
        k_mid4<<<CHUNK_BLOCKS, 256>>>(boff);   // L1 w4..7, pure-reg         (bufB in-place)
        k_fuse1<<<CHUNK_BLOCKS, 256>>>(boff);  // L1 w0..3 +D1+P1+ L2 w8..15 (bufB -> bufA)
        k_tail<<<CHUNK_BLOCKS, 256>>>(boff);   // L2 w4..7 + w0..3 + measure (bufA -> partials)
    }
    k_final<<<1, 128>>>(head_b, out);
}

// round 13
// speedup vs baseline: 1.0650x; 1.0650x over previous
#include <cuda_runtime.h>

#define BATCH 128
#define DIM   65536
#define NELEM (BATCH * DIM)

typedef unsigned long long u64;

// ---- scratch / precomputed tables (static device memory; no runtime allocs) ----
static __device__ float2 g_bufA[NELEM];          // 64 MB (holds real state as float)
static __device__ float2 g_bufB[NELEM];          // 64 MB
static __device__ float  g_partials[BATCH * 16];
static __device__ float2 g_cs[3][16];            // (cos(th/2), sin(th/2)) per layer/wire
static __device__ float2 g_Dhi[3][256];          // diagonal phase, wires 0..7  (bits 15..8)
static __device__ float2 g_Dlo[3][256];          // diagonal phase, wires 8..15 (bits 7..0)
static __device__ float  g_Ghi[256];             // head-weighted Z signs, wires 0..7
static __device__ float  g_Glo[256];             // head-weighted Z signs, wires 8..15

// ---- packed f32x2 helpers (FFMA2 path: PTX-only) ----
__device__ __forceinline__ u64 pk(float x, float y) {
    u64 r; asm("mov.b64 %0,{%1,%2};" : "=l"(r) : "f"(x), "f"(y)); return r;
}
__device__ __forceinline__ void upk(u64 a, float& x, float& y) {
    asm("mov.b64 {%0,%1},%2;" : "=f"(x), "=f"(y) : "l"(a));
}
__device__ __forceinline__ u64 fma2(u64 a, u64 b, u64 c) {
    u64 r; asm("fma.rn.f32x2 %0,%1,%2,%3;" : "=l"(r) : "l"(a), "l"(b), "l"(c)); return r;
}
__device__ __forceinline__ u64 mul2(u64 a, u64 b) {
    u64 r; asm("mul.rn.f32x2 %0,%1,%2;" : "=l"(r) : "l"(a), "l"(b)); return r;
}

// swizzles
__device__ __forceinline__ int swz(int i) {      // 3-term: f32 tiles (32-bank clean)
    return i ^ ((i >> 4) & 15) ^ (((i >> 8) & 1) << 4);
}
__device__ __forceinline__ int sw2(int i) {      // 2-term: u64 tiles (16-lane phases)
    return i ^ ((i >> 4) & 15);
}

// Pure suffix-XOR permutation (CNOT chain 0->1..->15, WITHOUT the ring-closing
// parity correction). dest bits 15..12 depend only on source bits 15..12.
__device__ __forceinline__ int permT(int a) {
    a ^= a >> 8; a ^= a >> 4; a ^= a >> 2; a ^= a >> 1;
    return a;
}
// Full composite permutation (T plus ring-closing CNOT: bit15 ^= parity).
__device__ __forceinline__ int permM(int a) {
    int t = permT(a);
    return t ^ ((t & 1) << 15);
}
__device__ __forceinline__ int sfx4(int m) { m ^= m >> 2; m ^= m >> 1; return m & 15; }

// 4 RY butterflies; local bit q of j <-> wire (wtop - q).
__device__ __forceinline__ void bfly4_real(float v[16], int layer, int wtop) {
#pragma unroll
    for (int q = 0; q < 4; q++) {
        float2 cs = g_cs[layer][wtop - q];
        float c = cs.x, s = cs.y;
#pragma unroll
        for (int j = 0; j < 16; j++) {
            if (!(j & (1 << q))) {
                int j1 = j | (1 << q);
                float x0 = v[j], x1 = v[j1];
                v[j]  = c * x0 - s * x1;
                v[j1] = s * x0 + c * x1;
            }
        }
    }
}

__device__ __forceinline__ void bfly4_pk(u64 v[16], int layer, int wtop) {
#pragma unroll
    for (int q = 0; q < 4; q++) {
        float2 cs = g_cs[layer][wtop - q];
        u64 cc = pk(cs.x, cs.x), sp = pk(cs.y, cs.y), sn = pk(-cs.y, -cs.y);
#pragma unroll
        for (int j = 0; j < 16; j++) {
            if (!(j & (1 << q))) {
                int j1 = j | (1 << q);
                u64 x0 = v[j], x1 = v[j1];
                v[j]  = fma2(sn, x1, mul2(cc, x0));
                v[j1] = fma2(sp, x0, mul2(cc, x1));
            }
        }
    }
}

// 3 butterflies on local bits 1..3 only (wires 14..12). Bit 0 (wire 15) is
// EXCLUDED: in T-stored space, flipping stored bit0 also flips true bit15, so
// the wire-15 butterfly must be applied elsewhere (in true space via shuffle).
__device__ __forceinline__ void bfly3_pk(u64 v[16], int layer) {
#pragma unroll
    for (int q = 1; q < 4; q++) {
        float2 cs = g_cs[layer][15 - q];
        u64 cc = pk(cs.x, cs.x), sp = pk(cs.y, cs.y), sn = pk(-cs.y, -cs.y);
#pragma unroll
        for (int j = 0; j < 16; j++) {
            if (!(j & (1 << q))) {
                int j1 = j | (1 << q);
                u64 x0 = v[j], x1 = v[j1];
                v[j]  = fma2(sn, x1, mul2(cc, x0));
                v[j1] = fma2(sp, x0, mul2(cc, x1));
            }
        }
    }
}

// Wire-15 butterfly in true space: partner lives in lane^1 (bit0 of lo), same
// register. even: c*x - s*px ; odd: s*px + c*x.
__device__ __forceinline__ u64 w15_bfly(u64 x, float c, float s, int odd) {
    u64 px = __shfl_xor_sync(0xFFFFFFFFu, x, 1);
    float coef = odd ? s : -s;
    return fma2(pk(coef, coef), px, mul2(pk(c, c), x));
}

// ---- precompute tables ----
__global__ void k_pre(const float* __restrict__ params, const float* __restrict__ head_w) {
    int t = threadIdx.x;  // 256
    if (t < 48) {
        int d = t >> 4, w = t & 15;
        float th = params[(d * 16 + w) * 2 + 0] * 0.5f;
        g_cs[d][w] = make_float2(cosf(th), sinf(th));
    }
    for (int d = 0; d < 3; d++) {
        float ah = 0.f, al = 0.f;
        for (int w = 0; w < 8; w++) {
            float ph = params[(d * 16 + w) * 2 + 1] * 0.5f;
            ah += ((t >> (7 - w)) & 1) ? -ph : ph;
        }
        for (int w = 8; w < 16; w++) {
            float ph = params[(d * 16 + w) * 2 + 1] * 0.5f;
            al += ((t >> (15 - w)) & 1) ? -ph : ph;
        }
        g_Dhi[d][t] = make_float2(cosf(ah), -sinf(ah));
        g_Dlo[d][t] = make_float2(cosf(al), -sinf(al));
    }
    float gh = 0.f, gl = 0.f;
    for (int w = 0; w < 8; w++)  gh += ((t >> (7 - w)) & 1)  ? -head_w[w] : head_w[w];
    for (int w = 8; w < 16; w++) gl += ((t >> (15 - w)) & 1) ? -head_w[w] : head_w[w];
    g_Ghi[t] = gh;
    g_Glo[t] = gl;
}

// ---- K1: L0 wires 0..3 (bits 15..12) + wires 8..15 (bits 7..0), real, natural space.
//      Tile {bits 15..12, 7..0}; block fixes bits 11..8 = jb. in -> bufA(real). ----
__global__ void __launch_bounds__(256) k1(const float* __restrict__ in) {
    __shared__ float tile[4096];
    float* out = (float*)(void*)g_bufA;
    int s = blockIdx.x >> 4, jb = blockIdx.x & 15;
    int sbase = s << 16;
    int t = threadIdx.x;                       // = lo (bits 7..0)
    {
        float v[16];
#pragma unroll
        for (int h = 0; h < 16; h++) v[h] = in[sbase | (h << 12) | (jb << 8) | t];
        bfly4_real(v, 0, 3);                   // bits 12..15 -> wires 3..0
#pragma unroll
        for (int h = 0; h < 16; h++) tile[swz((h << 8) | t)] = v[h];
    }
    __syncthreads();
    // stage: wires 8..11 (lo bits 7..4)
    {
        int h = t >> 4, m = t & 15;
        float w[16];
#pragma unroll
        for (int j = 0; j < 16; j++) w[j] = tile[swz((h << 8) | (j << 4) | m)];
        bfly4_real(w, 0, 11);
#pragma unroll
        for (int j = 0; j < 16; j++) tile[swz((h << 8) | (j << 4) | m)] = w[j];
    }
    __syncthreads();
    // stage: wires 12..15 (lo bits 3..0, natural space -> bit0 OK here)
    {
        int h = t >> 4, g = t & 15;
        float w[16];
#pragma unroll
        for (int j = 0; j < 16; j++) w[j] = tile[swz((h << 8) | (g << 4) | j)];
        bfly4_real(w, 0, 15);
        float4* o = (float4*)(out + (sbase | (h << 12) | (jb << 8) | (g << 4)));
#pragma unroll
        for (int m2 = 0; m2 < 4; m2++)
            o[m2] = make_float4(w[4 * m2], w[4 * m2 + 1], w[4 * m2 + 2], w[4 * m2 + 3]);
    }
}

// ---- K2: L0 wires 4..7 (bits 11..8) + D0 + T0-scatter + L1 wires {4..7, 8..11, 12..14}.
//      dest[15:12]=sfx4(hb) block-fixed; dest[11:0] dense in-tile.
//      bufA(real) -> bufB (T0-space). ----
__global__ void __launch_bounds__(256) k2() {
    __shared__ u64 st[4096];
    __shared__ float2 sDh[16];
    const float* in = (const float*)(const void*)g_bufA;
    u64* out = (u64*)(void*)g_bufB;
    int s = blockIdx.x >> 4, hb = blockIdx.x & 15;     // hb = bits 15..12
    int sbase = s << 16;
    int t = threadIdx.x;                               // bits 7..0
    if (t < 16) sDh[t] = g_Dhi[0][(hb << 4) | t];      // dh for j = t
    float2 dlo = g_Dlo[0][t];
    float v[16];
#pragma unroll
    for (int j = 0; j < 16; j++) v[j] = in[sbase | (hb << 12) | (j << 8) | t];
    bfly4_real(v, 0, 7);                       // bits 8..11 -> wires 7..4
    __syncthreads();                           // sDh visible; st untouched yet
#pragma unroll
    for (int j = 0; j < 16; j++) {
        int a = (hb << 12) | (j << 8) | t;
        int dest = permT(a);                   // dest[15:12] = sfx4(hb), block-fixed
        float2 dh = sDh[j];
        float dcr = dh.x * dlo.x - dh.y * dlo.y;
        float dci = dh.x * dlo.y + dh.y * dlo.x;
        st[sw2(dest & 4095)] = mul2(pk(v[j], v[j]), pk(dcr, dci));
    }
    __syncthreads();
    // stage 1: L1 wires 4..7 (u bits 11..8; stored-bit==true-bit for bits>=1)
    {
        u64 w[16];
#pragma unroll
        for (int j = 0; j < 16; j++) w[j] = st[sw2((j << 8) | t)];
        bfly4_pk(w, 1, 7);
#pragma unroll
        for (int j = 0; j < 16; j++) st[sw2((j << 8) | t)] = w[j];
    }
    __syncthreads();
    // stage 2: L1 wires 8..11 (u bits 7..4)
    {
        int k = t >> 4, m = t & 15;
        u64 w[16];
#pragma unroll
        for (int j = 0; j < 16; j++) w[j] = st[sw2((k << 8) | (j << 4) | m)];
        bfly4_pk(w, 1, 11);
#pragma unroll
        for (int j = 0; j < 16; j++) st[sw2((k << 8) | (j << 4) | m)] = w[j];
    }
    __syncthreads();
    // stage 3: L1 wires 12..14 ONLY (u bits 3..1; bit0=wire15 deferred to K3) + writeout
    {
        int k = t >> 4, g = t & 15;
        u64 w[16];
#pragma unroll
        for (int j = 0; j < 16; j++) w[j] = st[sw2((k << 8) | (g << 4) | j)];
        bfly3_pk(w, 1);
        int dhi = sfx4(hb);
        ulonglong2* o = (ulonglong2*)(out + (sbase | (dhi << 12) | (k << 8) | (g << 4)));
#pragma unroll
        for (int m2 = 0; m2 < 8; m2++) {
            ulonglong2 p; p.x = w[2 * m2]; p.y = w[2 * m2 + 1];
            o[m2] = p;
        }
    }
}

// ---- K3: relabel gather (T0 -> true) + L1 wire15 (shuffle) + L1 wires 0..3 + D1 +
//      T1-scatter + L2 wires {8..11, 12..14}. bufB -> bufA (T1-space). ----
__global__ void __launch_bounds__(256) k3() {
    __shared__ u64 st[4096];
    __shared__ float2 sDh[16];
    const u64* in = (const u64*)(const void*)g_bufB;
    u64* out = (u64*)(void*)g_bufA;
    int s = blockIdx.x >> 4, mid = blockIdx.x & 15;
    int lo = threadIdx.x;
    int sbase = s << 16;
    int abase = (mid << 8) | lo;
    if (lo < 16) sDh[lo] = g_Dhi[1][(lo << 4) | mid];
    int hx = (lo & 1) << 3;                    // deferred-parity relabel: flips bit15
    u64 v[16];
#pragma unroll
    for (int h = 0; h < 16; h++) v[h ^ hx] = in[sbase | (h << 12) | abase];
    // v[g] now holds TRUE state (g<<12)|abase.
    {   // L1 wire 15 (true bit 0 = lo&1): partner is lane^1, same register index.
        float2 c15 = g_cs[1][15];
        int odd = lo & 1;
#pragma unroll
        for (int g = 0; g < 16; g++) v[g] = w15_bfly(v[g], c15.x, c15.y, odd);
    }
    bfly4_pk(v, 1, 3);                         // L1 wires 3..0 (bits 15..12)
    float2 dlo = g_Dlo[1][lo];
    __syncthreads();
#pragma unroll
    for (int h = 0; h < 16; h++) {
        int a = (h << 12) | abase;
        int dest = permT(a);                   // T-only: rows dest[15:12]=sfx4(h)
        float2 dh = sDh[h];
        float dcr = dh.x * dlo.x - dh.y * dlo.y;
        float dci = dh.x * dlo.y + dh.y * dlo.x;
        float xr, xi; upk(v[h], xr, xi);
        u64 res = fma2(pk(xi, xi), pk(-dci, dcr), mul2(pk(xr, xr), pk(dcr, dci)));
        st[sw2(((dest >> 12) << 8) | (dest & 255))] = res;
    }
    __syncthreads();
    // stage S: L2 wires 8..11 (dest bits 7..4)
    {
        int k = threadIdx.x >> 4, m = threadIdx.x & 15;
        u64 w[16];
#pragma unroll
        for (int j = 0; j < 16; j++) w[j] = st[sw2((k << 8) | (j << 4) | m)];
        bfly4_pk(w, 2, 11);
#pragma unroll
        for (int j = 0; j < 16; j++) st[sw2((k << 8) | (j << 4) | m)] = w[j];
    }
    __syncthreads();
    // stage T: L2 wires 12..14 ONLY (dest bits 3..1; wire15 deferred to K4) + writeout
    {
        int k = threadIdx.x >> 4, g = threadIdx.x & 15;
        u64 w[16];
#pragma unroll
        for (int j = 0; j < 16; j++) w[j] = st[sw2((k << 8) | (g << 4) | j)];
        bfly3_pk(w, 2);
        int ms = sfx4(mid);
        int H = (k << 4) | (ms ^ ((k & 1) ? 15 : 0));  // dest bits 8..15 (row-implied)
        ulonglong2* o = (ulonglong2*)(out + (sbase | (H << 8) | (g << 4)));
#pragma unroll
        for (int m2 = 0; m2 < 8; m2++) {
            ulonglong2 p; p.x = w[2 * m2]; p.y = w[2 * m2 + 1];
            o[m2] = p;
        }
    }
}

// ---- K4: relabel gather (T1 -> true) + L2 wire15 (shuffle) + L2 wires 4..7 +
//      wires 0..3 + fused measurement (D2 skipped; ring via permM in sign lookup).
//      bufA -> partials. ----
__global__ void __launch_bounds__(256) k4() {
    __shared__ u64 st[4096];
    __shared__ float sGhi[256], sGlo[256];
    const u64* in = (const u64*)(const void*)g_bufA;
    int s = blockIdx.x >> 4, lch = blockIdx.x & 15;
    int loBase = lch << 4;
    int sbase = s << 16;
    int t = threadIdx.x;
    sGhi[t] = g_Ghi[t];
    sGlo[t] = g_Glo[t];
    // load tile (bits 15..8 x 16 lo), applying deferred-parity relabel (flip bit15 <-> HH bit7)
    {
        int l = t & 15, Ho = t >> 4;
        int hx = (l & 1) << 7;                 // thread-fixed
#pragma unroll
        for (int i = 0; i < 16; i++) {
            int HH = Ho + (i << 4);
            st[((HH ^ hx) << 4) | l] = in[sbase | (HH << 8) | (loBase + l)];
        }
    }
    __syncthreads();
    // stage A: L2 wire 15 (shuffle, true bit0 = l&1 -> partner thread t^1)
    //          then wires 4..7 (HH bits 0..3 = global bits 8..11)
    {
        int Hhi = t >> 4, l = t & 15;
        float2 c15 = g_cs[2][15];
        int odd = l & 1;
        u64 w[16];
#pragma unroll
        for (int j = 0; j < 16; j++) w[j] = st[(Hhi << 8) | (j << 4) | l];
#pragma unroll
        for (int j = 0; j < 16; j++) w[j] = w15_bfly(w[j], c15.x, c15.y, odd);
        bfly4_pk(w, 2, 7);
#pragma unroll
        for (int j = 0; j < 16; j++) st[(Hhi << 8) | (j << 4) | l] = w[j];
    }
    __syncthreads();
    // stage B: wires 0..3 (HH bits 4..7 = global bits 12..15) + measurement
    float acc = 0.f;
    {
        int Hlo = t >> 4, l = t & 15;
        u64 w[16];
#pragma unroll
        for (int j = 0; j < 16; j++) w[j] = st[(j << 8) | (Hlo << 4) | l];
        bfly4_pk(w, 2, 3);
        u64 accP = pk(0.f, 0.f);
#pragma unroll
        for (int j = 0; j < 16; j++) {
            int HH = (j << 4) | Hlo;
            int y = permM((HH << 8) | (loBase + l));
            float g = sGhi[(y >> 8) & 255] + sGlo[y & 255];
            accP = fma2(w[j], mul2(w[j], pk(g, g)), accP);
        }
        float ar, ai; upk(accP, ar, ai);
        acc = ar + ai;
    }
#pragma unroll
    for (int o = 16; o; o >>= 1) acc += __shfl_xor_sync(0xFFFFFFFFu, acc, o);
    __shared__ float red[8];
    if ((t & 31) == 0) red[t >> 5] = acc;
    __syncthreads();
    if (t == 0) {
        float tt = 0.f;
#pragma unroll
        for (int i = 0; i < 8; i++) tt += red[i];
        g_partials[blockIdx.x] = tt;
    }
}

__global__ void k_final(const float* __restrict__ head_b, float* __restrict__ out) {
    int s = threadIdx.x;  // 128
    float a = 0.f;
#pragma unroll
    for (int m = 0; m < 16; m++) a += g_partials[(s << 4) + m];
    out[s] = head_b[0] + a;
}

extern "C" void kernel_launch(void* const* d_in, const int* in_sizes, int n_in,
                              void* d_out, int out_size) {
    const float* state  = (const float*)d_in[0];  // (128, 65536)
    const float* params = (const float*)d_in[1];  // (3, 16, 2)
    const float* head_w = (const float*)d_in[2];  // (1, 16)
    const float* head_b = (const float*)d_in[3];  // (1,)
    float* out = (float*)d_out;                   // (128,)
    (void)in_sizes; (void)n_in; (void)out_size;

    k_pre<<<1, 256>>>(params, head_w);
    k1<<<2048, 256>>>(state);  // L0 w0..3 + w8..15                  (state -> bufA, real)
    k2<<<2048, 256>>>();       // L0 w4..7 +D0+T0+ L1 w4..14         (bufA -> bufB, T0)
    k3<<<2048, 256>>>();       // L1 w15,w0..3 +D1+T1+ L2 w8..14     (bufB -> bufA, T1)
    k4<<<2048, 256>>>();       // L2 w15,w4..7,w0..3 + measure       (bufA -> partials)
    k_final<<<1, 128>>>(head_b, out);
}

// round 15
// speedup vs baseline: 1.3258x; 1.2449x over previous
#include <cuda_runtime.h>
#include <cuda_fp16.h>

#define BATCH 128
#define DIM   65536
#define NELEM (BATCH * DIM)

typedef unsigned long long u64;
typedef unsigned int u32;

// ---- scratch / precomputed tables (static device memory; no runtime allocs) ----
static __device__ float2 g_bufA[NELEM];          // 64 MB (used as half / half2 views)
static __device__ float2 g_bufB[NELEM];          // 64 MB (used as half2 view)
static __device__ float  g_partials[BATCH * 16];
static __device__ float2 g_cs[3][16];            // (cos(th/2), sin(th/2)) per layer/wire
static __device__ float2 g_Dhi[3][256];          // diagonal phase, wires 0..7  (bits 15..8)
static __device__ float2 g_Dlo[3][256];          // diagonal phase, wires 8..15 (bits 7..0)
static __device__ float  g_Ghi[256];             // head-weighted Z signs, wires 0..7
static __device__ float  g_Glo[256];             // head-weighted Z signs, wires 8..15

// ---- packed f32x2 helpers (FFMA2 path: PTX-only) ----
__device__ __forceinline__ u64 pk(float x, float y) {
    u64 r; asm("mov.b64 %0,{%1,%2};" : "=l"(r) : "f"(x), "f"(y)); return r;
}
__device__ __forceinline__ void upk(u64 a, float& x, float& y) {
    asm("mov.b64 {%0,%1},%2;" : "=f"(x), "=f"(y) : "l"(a));
}
__device__ __forceinline__ u64 fma2(u64 a, u64 b, u64 c) {
    u64 r; asm("fma.rn.f32x2 %0,%1,%2,%3;" : "=l"(r) : "l"(a), "l"(b), "l"(c)); return r;
}
__device__ __forceinline__ u64 mul2(u64 a, u64 b) {
    u64 r; asm("mul.rn.f32x2 %0,%1,%2;" : "=l"(r) : "l"(a), "l"(b)); return r;
}

// ---- fp16 pack/unpack (storage only; all math stays fp32) ----
// half2 bits: low half = first (re), high half = second (im).
__device__ __forceinline__ u32 f2h2(float x, float y) {
    u32 r; asm("cvt.rn.f16x2.f32 %0,%1,%2;" : "=r"(r) : "f"(y), "f"(x)); return r;
}
__device__ __forceinline__ u32 h2_from_pk(u64 a) {
    float x, y; upk(a, x, y); return f2h2(x, y);
}
__device__ __forceinline__ u64 pk_from_h2(u32 u) {
    float lo, hi;
    asm("{.reg .f16 a,b; mov.b32 {a,b},%2; cvt.f32.f16 %0,a; cvt.f32.f16 %1,b;}"
        : "=f"(lo), "=f"(hi) : "r"(u));
    return pk(lo, hi);
}

// swizzles
__device__ __forceinline__ int swz(int i) {      // 3-term: f32 tiles (32-bank clean)
    return i ^ ((i >> 4) & 15) ^ (((i >> 8) & 1) << 4);
}
__device__ __forceinline__ int sw2(int i) {      // 2-term: u64 tiles (16-lane phases)
    return i ^ ((i >> 4) & 15);
}

// Pure suffix-XOR permutation (CNOT chain 0->1..->15, WITHOUT the ring-closing
// parity correction). dest bits 15..12 depend only on source bits 15..12.
__device__ __forceinline__ int permT(int a) {
    a ^= a >> 8; a ^= a >> 4; a ^= a >> 2; a ^= a >> 1;
    return a;
}
// Full composite permutation (T plus ring-closing CNOT: bit15 ^= parity).
__device__ __forceinline__ int permM(int a) {
    int t = permT(a);
    return t ^ ((t & 1) << 15);
}
__device__ __forceinline__ int sfx4(int m) { m ^= m >> 2; m ^= m >> 1; return m & 15; }

// 4 RY butterflies; local bit q of j <-> wire (wtop - q).
__device__ __forceinline__ void bfly4_real(float v[16], int layer, int wtop) {
#pragma unroll
    for (int q = 0; q < 4; q++) {
        float2 cs = g_cs[layer][wtop - q];
        float c = cs.x, s = cs.y;
#pragma unroll
        for (int j = 0; j < 16; j++) {
            if (!(j & (1 << q))) {
                int j1 = j | (1 << q);
                float x0 = v[j], x1 = v[j1];
                v[j]  = c * x0 - s * x1;
                v[j1] = s * x0 + c * x1;
            }
        }
    }
}

__device__ __forceinline__ void bfly4_pk(u64 v[16], int layer, int wtop) {
#pragma unroll
    for (int q = 0; q < 4; q++) {
        float2 cs = g_cs[layer][wtop - q];
        u64 cc = pk(cs.x, cs.x), sp = pk(cs.y, cs.y), sn = pk(-cs.y, -cs.y);
#pragma unroll
        for (int j = 0; j < 16; j++) {
            if (!(j & (1 << q))) {
                int j1 = j | (1 << q);
                u64 x0 = v[j], x1 = v[j1];
                v[j]  = fma2(sn, x1, mul2(cc, x0));
                v[j1] = fma2(sp, x0, mul2(cc, x1));
            }
        }
    }
}

// 3 butterflies on local bits 1..3 only (wires 14..12). Bit 0 (wire 15) is
// EXCLUDED: in T-stored space, flipping stored bit0 also flips true bit15, so
// the wire-15 butterfly must be applied elsewhere (in true space via shuffle).
__device__ __forceinline__ void bfly3_pk(u64 v[16], int layer) {
#pragma unroll
    for (int q = 1; q < 4; q++) {
        float2 cs = g_cs[layer][15 - q];
        u64 cc = pk(cs.x, cs.x), sp = pk(cs.y, cs.y), sn = pk(-cs.y, -cs.y);
#pragma unroll
        for (int j = 0; j < 16; j++) {
            if (!(j & (1 << q))) {
                int j1 = j | (1 << q);
                u64 x0 = v[j], x1 = v[j1];
                v[j]  = fma2(sn, x1, mul2(cc, x0));
                v[j1] = fma2(sp, x0, mul2(cc, x1));
            }
        }
    }
}

// Wire-15 butterfly in true space: partner lives in lane^1 (bit0 of lo), same
// register. even: c*x - s*px ; odd: s*px + c*x.
__device__ __forceinline__ u64 w15_bfly(u64 x, float c, float s, int odd) {
    u64 px = __shfl_xor_sync(0xFFFFFFFFu, x, 1);
    float coef = odd ? s : -s;
    return fma2(pk(coef, coef), px, mul2(pk(c, c), x));
}

// ---- precompute tables ----
__global__ void k_pre(const float* __restrict__ params, const float* __restrict__ head_w) {
    int t = threadIdx.x;  // 256
    if (t < 48) {
        int d = t >> 4, w = t & 15;
        float th = params[(d * 16 + w) * 2 + 0] * 0.5f;
        g_cs[d][w] = make_float2(cosf(th), sinf(th));
    }
    for (int d = 0; d < 3; d++) {
        float ah = 0.f, al = 0.f;
        for (int w = 0; w < 8; w++) {
            float ph = params[(d * 16 + w) * 2 + 1] * 0.5f;
            ah += ((t >> (7 - w)) & 1) ? -ph : ph;
        }
        for (int w = 8; w < 16; w++) {
            float ph = params[(d * 16 + w) * 2 + 1] * 0.5f;
            al += ((t >> (15 - w)) & 1) ? -ph : ph;
        }
        g_Dhi[d][t] = make_float2(cosf(ah), -sinf(ah));
        g_Dlo[d][t] = make_float2(cosf(al), -sinf(al));
    }
    float gh = 0.f, gl = 0.f;
    for (int w = 0; w < 8; w++)  gh += ((t >> (7 - w)) & 1)  ? -head_w[w] : head_w[w];
    for (int w = 8; w < 16; w++) gl += ((t >> (15 - w)) & 1) ? -head_w[w] : head_w[w];
    g_Ghi[t] = gh;
    g_Glo[t] = gl;
}

// ---- K1: L0 wires 0..3 (bits 15..12) + wires 8..15 (bits 7..0), real, natural space.
//      Tile {bits 15..12, 7..0}; block fixes bits 11..8 = jb. in(f32) -> bufA(half). ----
__global__ void __launch_bounds__(256) k1(const float* __restrict__ in) {
    __shared__ float tile[4096];
    __half* out = (__half*)(void*)g_bufA;
    int s = blockIdx.x >> 4, jb = blockIdx.x & 15;
    int sbase = s << 16;
    int t = threadIdx.x;                       // = lo (bits 7..0)
    {
        float v[16];
#pragma unroll
        for (int h = 0; h < 16; h++) v[h] = in[sbase | (h << 12) | (jb << 8) | t];
        bfly4_real(v, 0, 3);                   // bits 12..15 -> wires 3..0
#pragma unroll
        for (int h = 0; h < 16; h++) tile[swz((h << 8) | t)] = v[h];
    }
    __syncthreads();
    // stage: wires 8..11 (lo bits 7..4)
    {
        int h = t >> 4, m = t & 15;
        float w[16];
#pragma unroll
        for (int j = 0; j < 16; j++) w[j] = tile[swz((h << 8) | (j << 4) | m)];
        bfly4_real(w, 0, 11);
#pragma unroll
        for (int j = 0; j < 16; j++) tile[swz((h << 8) | (j << 4) | m)] = w[j];
    }
    __syncthreads();
    // stage: wires 12..15 (lo bits 3..0, natural space) -> half output, 32B runs
    {
        int h = t >> 4, g = t & 15;
        float w[16];
#pragma unroll
        for (int j = 0; j < 16; j++) w[j] = tile[swz((h << 8) | (g << 4) | j)];
        bfly4_real(w, 0, 15);
        u32 o8[8];
#pragma unroll
        for (int m2 = 0; m2 < 8; m2++) o8[m2] = f2h2(w[2 * m2], w[2 * m2 + 1]);
        uint4* o = (uint4*)(out + (sbase | (h << 12) | (jb << 8) | (g << 4)));
        o[0] = make_uint4(o8[0], o8[1], o8[2], o8[3]);
        o[1] = make_uint4(o8[4], o8[5], o8[6], o8[7]);
    }
}

// ---- K2: L0 wires 4..7 (bits 11..8) + D0 + T0-scatter + L1 wires {4..7, 8..11, 12..14}.
//      dest[15:12]=sfx4(hb) block-fixed; dest[11:0] dense in-tile.
//      bufA(half real) -> bufB (half2, T0-space). ----
__global__ void __launch_bounds__(256) k2() {
    __shared__ u64 st[4096];
    __shared__ float2 sDh[16];
    const __half* in = (const __half*)(const void*)g_bufA;
    u32* out = (u32*)(void*)g_bufB;
    int s = blockIdx.x >> 4, hb = blockIdx.x & 15;     // hb = bits 15..12
    int sbase = s << 16;
    int t = threadIdx.x;                               // bits 7..0
    if (t < 16) sDh[t] = g_Dhi[0][(hb << 4) | t];      // dh for j = t
    float2 dlo = g_Dlo[0][t];
    float v[16];
#pragma unroll
    for (int j = 0; j < 16; j++) v[j] = __half2float(in[sbase | (hb << 12) | (j << 8) | t]);
    bfly4_real(v, 0, 7);                       // bits 8..11 -> wires 7..4
    __syncthreads();                           // sDh visible; st untouched yet
#pragma unroll
    for (int j = 0; j < 16; j++) {
        int a = (hb << 12) | (j << 8) | t;
        int dest = permT(a);                   // dest[15:12] = sfx4(hb), block-fixed
        float2 dh = sDh[j];
        float dcr = dh.x * dlo.x - dh.y * dlo.y;
        float dci = dh.x * dlo.y + dh.y * dlo.x;
        st[sw2(dest & 4095)] = mul2(pk(v[j], v[j]), pk(dcr, dci));
    }
    __syncthreads();
    // stage 1: L1 wires 4..7 (u bits 11..8; stored-bit==true-bit for bits>=1)
    {
        u64 w[16];
#pragma unroll
        for (int j = 0; j < 16; j++) w[j] = st[sw2((j << 8) | t)];
        bfly4_pk(w, 1, 7);
#pragma unroll
        for (int j = 0; j < 16; j++) st[sw2((j << 8) | t)] = w[j];
    }
    __syncthreads();
    // stage 2: L1 wires 8..11 (u bits 7..4)
    {
        int k = t >> 4, m = t & 15;
        u64 w[16];
#pragma unroll
        for (int j = 0; j < 16; j++) w[j] = st[sw2((k << 8) | (j << 4) | m)];
        bfly4_pk(w, 1, 11);
#pragma unroll
        for (int j = 0; j < 16; j++) st[sw2((k << 8) | (j << 4) | m)] = w[j];
    }
    __syncthreads();
    // stage 3: L1 wires 12..14 ONLY (u bits 3..1; bit0=wire15 deferred) + half2 writeout
    {
        int k = t >> 4, g = t & 15;
        u64 w[16];
#pragma unroll
        for (int j = 0; j < 16; j++) w[j] = st[sw2((k << 8) | (g << 4) | j)];
        bfly3_pk(w, 1);
        u32 o16[16];
#pragma unroll
        for (int j = 0; j < 16; j++) o16[j] = h2_from_pk(w[j]);
        int dhi = sfx4(hb);
        uint4* o = (uint4*)(out + (sbase | (dhi << 12) | (k << 8) | (g << 4)));
#pragma unroll
        for (int m2 = 0; m2 < 4; m2++)
            o[m2] = make_uint4(o16[4 * m2], o16[4 * m2 + 1], o16[4 * m2 + 2], o16[4 * m2 + 3]);
    }
}

// ---- K3: relabel gather (T0 -> true) + L1 wire15 (shuffle) + L1 wires 0..3 + D1 +
//      T1-scatter + L2 wires {8..11, 12..14}. bufB(half2) -> bufA(half2, T1-space). ----
__global__ void __launch_bounds__(256) k3() {
    __shared__ u64 st[4096];
    __shared__ float2 sDh[16];
    const u32* in = (const u32*)(const void*)g_bufB;
    u32* out = (u32*)(void*)g_bufA;
    int s = blockIdx.x >> 4, mid = blockIdx.x & 15;
    int lo = threadIdx.x;
    int sbase = s << 16;
    int abase = (mid << 8) | lo;
    if (lo < 16) sDh[lo] = g_Dhi[1][(lo << 4) | mid];
    int hx = (lo & 1) << 3;                    // deferred-parity relabel: flips bit15
    u64 v[16];
#pragma unroll
    for (int h = 0; h < 16; h++) v[h ^ hx] = pk_from_h2(in[sbase | (h << 12) | abase]);
    // v[g] now holds TRUE state (g<<12)|abase.
    {   // L1 wire 15 (true bit 0 = lo&1): partner is lane^1, same register index.
        float2 c15 = g_cs[1][15];
        int odd = lo & 1;
#pragma unroll
        for (int g = 0; g < 16; g++) v[g] = w15_bfly(v[g], c15.x, c15.y, odd);
    }
    bfly4_pk(v, 1, 3);                         // L1 wires 3..0 (bits 15..12)
    float2 dlo = g_Dlo[1][lo];
    __syncthreads();
#pragma unroll
    for (int h = 0; h < 16; h++) {
        int a = (h << 12) | abase;
        int dest = permT(a);                   // T-only: rows dest[15:12]=sfx4(h)
        float2 dh = sDh[h];
        float dcr = dh.x * dlo.x - dh.y * dlo.y;
        float dci = dh.x * dlo.y + dh.y * dlo.x;
        float xr, xi; upk(v[h], xr, xi);
        u64 res = fma2(pk(xi, xi), pk(-dci, dcr), mul2(pk(xr, xr), pk(dcr, dci)));
        st[sw2(((dest >> 12) << 8) | (dest & 255))] = res;
    }
    __syncthreads();
    // stage S: L2 wires 8..11 (dest bits 7..4)
    {
        int k = threadIdx.x >> 4, m = threadIdx.x & 15;
        u64 w[16];
#pragma unroll
        for (int j = 0; j < 16; j++) w[j] = st[sw2((k << 8) | (j << 4) | m)];
        bfly4_pk(w, 2, 11);
#pragma unroll
        for (int j = 0; j < 16; j++) st[sw2((k << 8) | (j << 4) | m)] = w[j];
    }
    __syncthreads();
    // stage T: L2 wires 12..14 ONLY (dest bits 3..1; wire15 deferred to K4) + writeout
    {
        int k = threadIdx.x >> 4, g = threadIdx.x & 15;
        u64 w[16];
#pragma unroll
        for (int j = 0; j < 16; j++) w[j] = st[sw2((k << 8) | (g << 4) | j)];
        bfly3_pk(w, 2);
        u32 o16[16];
#pragma unroll
        for (int j = 0; j < 16; j++) o16[j] = h2_from_pk(w[j]);
        int ms = sfx4(mid);
        int H = (k << 4) | (ms ^ ((k & 1) ? 15 : 0));  // dest bits 8..15 (row-implied)
        uint4* o = (uint4*)(out + (sbase | (H << 8) | (g << 4)));
#pragma unroll
        for (int m2 = 0; m2 < 4; m2++)
            o[m2] = make_uint4(o16[4 * m2], o16[4 * m2 + 1], o16[4 * m2 + 2], o16[4 * m2 + 3]);
    }
}

// ---- K4: relabel gather (T1 -> true) + L2 wire15 (shuffle) + L2 wires 4..7 +
//      wires 0..3 + fused measurement (D2 skipped; ring via permM in sign lookup).
//      bufA(half2) -> partials. ----
__global__ void __launch_bounds__(256) k4() {
    __shared__ u64 st[4096];
    __shared__ float sGhi[256], sGlo[256];
    const u32* in = (const u32*)(const void*)g_bufA;
    int s = blockIdx.x >> 4, lch = blockIdx.x & 15;
    int loBase = lch << 4;
    int sbase = s << 16;
    int t = threadIdx.x;
    sGhi[t] = g_Ghi[t];
    sGlo[t] = g_Glo[t];
    // load tile (bits 15..8 x 16 lo), applying deferred-parity relabel (flip bit15 <-> HH bit7)
    {
        int l = t & 15, Ho = t >> 4;
        int hx = (l & 1) << 7;                 // thread-fixed
#pragma unroll
        for (int i = 0; i < 16; i++) {
            int HH = Ho + (i << 4);
            st[((HH ^ hx) << 4) | l] = pk_from_h2(in[sbase | (HH << 8) | (loBase + l)]);
        }
    }
    __syncthreads();
    // stage A: L2 wire 15 (shuffle, true bit0 = l&1 -> partner thread t^1)
    //          then wires 4..7 (HH bits 0..3 = global bits 8..11)
    {
        int Hhi = t >> 4, l = t & 15;
        float2 c15 = g_cs[2][15];
        int odd = l & 1;
        u64 w[16];
#pragma unroll
        for (int j = 0; j < 16; j++) w[j] = st[(Hhi << 8) | (j << 4) | l];
#pragma unroll
        for (int j = 0; j < 16; j++) w[j] = w15_bfly(w[j], c15.x, c15.y, odd);
        bfly4_pk(w, 2, 7);
#pragma unroll
        for (int j = 0; j < 16; j++) st[(Hhi << 8) | (j << 4) | l] = w[j];
    }
    __syncthreads();
    // stage B: wires 0..3 (HH bits 4..7 = global bits 12..15) + measurement
    float acc = 0.f;
    {
        int Hlo = t >> 4, l = t & 15;
        u64 w[16];
#pragma unroll
        for (int j = 0; j < 16; j++) w[j] = st[(j << 8) | (Hlo << 4) | l];
        bfly4_pk(w, 2, 3);
        u64 accP = pk(0.f, 0.f);
#pragma unroll
        for (int j = 0; j < 16; j++) {
            int HH = (j << 4) | Hlo;
            int y = permM((HH << 8) | (loBase + l));
            float g = sGhi[(y >> 8) & 255] + sGlo[y & 255];
            accP = fma2(w[j], mul2(w[j], pk(g, g)), accP);
        }
        float ar, ai; upk(accP, ar, ai);
        acc = ar + ai;
    }
#pragma unroll
    for (int o = 16; o; o >>= 1) acc += __shfl_xor_sync(0xFFFFFFFFu, acc, o);
    __shared__ float red[8];
    if ((t & 31) == 0) red[t >> 5] = acc;
    __syncthreads();
    if (t == 0) {
        float tt = 0.f;
#pragma unroll
        for (int i = 0; i < 8; i++) tt += red[i];
        g_partials[blockIdx.x] = tt;
    }
}

__global__ void k_final(const float* __restrict__ head_b, float* __restrict__ out) {
    int s = threadIdx.x;  // 128
    float a = 0.f;
#pragma unroll
    for (int m = 0; m < 16; m++) a += g_partials[(s << 4) + m];
    out[s] = head_b[0] + a;
}

extern "C" void kernel_launch(void* const* d_in, const int* in_sizes, int n_in,
                              void* d_out, int out_size) {
    const float* state  = (const float*)d_in[0];  // (128, 65536)
    const float* params = (const float*)d_in[1];  // (3, 16, 2)
    const float* head_w = (const float*)d_in[2];  // (1, 16)
    const float* head_b = (const float*)d_in[3];  // (1,)
    float* out = (float*)d_out;                   // (128,)
    (void)in_sizes; (void)n_in; (void)out_size;

    k_pre<<<1, 256>>>(params, head_w);
    k1<<<2048, 256>>>(state);  // L0 w0..3 + w8..15                  (f32 -> bufA half)
    k2<<<2048, 256>>>();       // L0 w4..7 +D0+T0+ L1 w4..14         (half -> bufB half2, T0)
    k3<<<2048, 256>>>();       // L1 w15,w0..3 +D1+T1+ L2 w8..14     (bufB -> bufA half2, T1)
    k4<<<2048, 256>>>();       // L2 w15,w4..7,w0..3 + measure       (bufA -> partials)
    k_final<<<1, 128>>>(head_b, out);
}

// round 16
// speedup vs baseline: 1.3262x; 1.0003x over previous
#include <cuda_runtime.h>
#include <cuda_fp16.h>

#define BATCH 128
#define DIM   65536
#define NELEM (BATCH * DIM)

typedef unsigned long long u64;
typedef unsigned int u32;

// ---- scratch / precomputed tables (static device memory; no runtime allocs) ----
static __device__ float2 g_bufA[NELEM];          // 64 MB (used as half / half2 views)
static __device__ float2 g_bufB[NELEM];          // 64 MB (used as half2 view)
static __device__ float  g_partials[BATCH * 16];
static __device__ float2 g_cs[3][16];            // (cos(th/2), sin(th/2)) per layer/wire
static __device__ float2 g_Dhi[3][256];          // diagonal phase, wires 0..7  (bits 15..8)
static __device__ float2 g_Dlo[3][256];          // diagonal phase, wires 8..15 (bits 7..0)
static __device__ float  g_Ghi[256];             // head-weighted Z signs, wires 0..7
static __device__ float  g_Glo[256];             // head-weighted Z signs, wires 8..15

// ---- packed f32x2 helpers (FFMA2 path: PTX-only) ----
__device__ __forceinline__ u64 pk(float x, float y) {
    u64 r; asm("mov.b64 %0,{%1,%2};" : "=l"(r) : "f"(x), "f"(y)); return r;
}
__device__ __forceinline__ void upk(u64 a, float& x, float& y) {
    asm("mov.b64 {%0,%1},%2;" : "=f"(x), "=f"(y) : "l"(a));
}
__device__ __forceinline__ u64 fma2(u64 a, u64 b, u64 c) {
    u64 r; asm("fma.rn.f32x2 %0,%1,%2,%3;" : "=l"(r) : "l"(a), "l"(b), "l"(c)); return r;
}
__device__ __forceinline__ u64 mul2(u64 a, u64 b) {
    u64 r; asm("mul.rn.f32x2 %0,%1,%2;" : "=l"(r) : "l"(a), "l"(b)); return r;
}

// ---- fp16 pack/unpack (storage only; all math stays fp32) ----
// half2 bits: low half = first (re), high half = second (im).
__device__ __forceinline__ u32 f2h2(float x, float y) {
    u32 r; asm("cvt.rn.f16x2.f32 %0,%1,%2;" : "=r"(r) : "f"(y), "f"(x)); return r;
}
__device__ __forceinline__ u32 h2_from_pk(u64 a) {
    float x, y; upk(a, x, y); return f2h2(x, y);
}
__device__ __forceinline__ u64 pk_from_h2(u32 u) {
    float lo, hi;
    asm("{.reg .f16 a,b; mov.b32 {a,b},%2; cvt.f32.f16 %0,a; cvt.f32.f16 %1,b;}"
        : "=f"(lo), "=f"(hi) : "r"(u));
    return pk(lo, hi);
}

// swizzles
__device__ __forceinline__ int swz(int i) {      // 3-term: f32 tiles (32-bank clean)
    return i ^ ((i >> 4) & 15) ^ (((i >> 8) & 1) << 4);
}
__device__ __forceinline__ int sw2(int i) {      // 2-term: u64 tiles (16-lane phases)
    return i ^ ((i >> 4) & 15);
}

// Pure suffix-XOR permutation (CNOT chain 0->1..->15, WITHOUT the ring-closing
// parity correction). dest bits 15..12 depend only on source bits 15..12.
__device__ __forceinline__ int permT(int a) {
    a ^= a >> 8; a ^= a >> 4; a ^= a >> 2; a ^= a >> 1;
    return a;
}
// Full composite permutation (T plus ring-closing CNOT: bit15 ^= parity).
__device__ __forceinline__ int permM(int a) {
    int t = permT(a);
    return t ^ ((t & 1) << 15);
}
__device__ __forceinline__ int sfx4(int m) { m ^= m >> 2; m ^= m >> 1; return m & 15; }

// 4 RY butterflies; local bit q of j <-> wire (wtop - q).
__device__ __forceinline__ void bfly4_real(float v[16], int layer, int wtop) {
#pragma unroll
    for (int q = 0; q < 4; q++) {
        float2 cs = g_cs[layer][wtop - q];
        float c = cs.x, s = cs.y;
#pragma unroll
        for (int j = 0; j < 16; j++) {
            if (!(j & (1 << q))) {
                int j1 = j | (1 << q);
                float x0 = v[j], x1 = v[j1];
                v[j]  = c * x0 - s * x1;
                v[j1] = s * x0 + c * x1;
            }
        }
    }
}

__device__ __forceinline__ void bfly4_pk(u64 v[16], int layer, int wtop) {
#pragma unroll
    for (int q = 0; q < 4; q++) {
        float2 cs = g_cs[layer][wtop - q];
        u64 cc = pk(cs.x, cs.x), sp = pk(cs.y, cs.y), sn = pk(-cs.y, -cs.y);
#pragma unroll
        for (int j = 0; j < 16; j++) {
            if (!(j & (1 << q))) {
                int j1 = j | (1 << q);
                u64 x0 = v[j], x1 = v[j1];
                v[j]  = fma2(sn, x1, mul2(cc, x0));
                v[j1] = fma2(sp, x0, mul2(cc, x1));
            }
        }
    }
}

// 3 butterflies on local bits 1..3 only (wires 14..12). Bit 0 (wire 15) is
// EXCLUDED: in T-stored space, flipping stored bit0 also flips true bit15, so
// the wire-15 butterfly must be applied elsewhere (in true space via shuffle).
__device__ __forceinline__ void bfly3_pk(u64 v[16], int layer) {
#pragma unroll
    for (int q = 1; q < 4; q++) {
        float2 cs = g_cs[layer][15 - q];
        u64 cc = pk(cs.x, cs.x), sp = pk(cs.y, cs.y), sn = pk(-cs.y, -cs.y);
#pragma unroll
        for (int j = 0; j < 16; j++) {
            if (!(j & (1 << q))) {
                int j1 = j | (1 << q);
                u64 x0 = v[j], x1 = v[j1];
                v[j]  = fma2(sn, x1, mul2(cc, x0));
                v[j1] = fma2(sp, x0, mul2(cc, x1));
            }
        }
    }
}

// Wire-15 butterfly in true space: partner lives in lane^1 (bit0 of lo), same
// register. even: c*x - s*px ; odd: s*px + c*x.
__device__ __forceinline__ u64 w15_bfly(u64 x, float c, float s, int odd) {
    u64 px = __shfl_xor_sync(0xFFFFFFFFu, x, 1);
    float coef = odd ? s : -s;
    return fma2(pk(coef, coef), px, mul2(pk(c, c), x));
}

// ---- precompute tables ----
__global__ void k_pre(const float* __restrict__ params, const float* __restrict__ head_w) {
    int t = threadIdx.x;  // 256
    if (t < 48) {
        int d = t >> 4, w = t & 15;
        float th = params[(d * 16 + w) * 2 + 0] * 0.5f;
        g_cs[d][w] = make_float2(cosf(th), sinf(th));
    }
    for (int d = 0; d < 3; d++) {
        float ah = 0.f, al = 0.f;
        for (int w = 0; w < 8; w++) {
            float ph = params[(d * 16 + w) * 2 + 1] * 0.5f;
            ah += ((t >> (7 - w)) & 1) ? -ph : ph;
        }
        for (int w = 8; w < 16; w++) {
            float ph = params[(d * 16 + w) * 2 + 1] * 0.5f;
            al += ((t >> (15 - w)) & 1) ? -ph : ph;
        }
        g_Dhi[d][t] = make_float2(cosf(ah), -sinf(ah));
        g_Dlo[d][t] = make_float2(cosf(al), -sinf(al));
    }
    float gh = 0.f, gl = 0.f;
    for (int w = 0; w < 8; w++)  gh += ((t >> (7 - w)) & 1)  ? -head_w[w] : head_w[w];
    for (int w = 8; w < 16; w++) gl += ((t >> (15 - w)) & 1) ? -head_w[w] : head_w[w];
    g_Ghi[t] = gh;
    g_Glo[t] = gl;
}

// ---- K1: L0 wires 0..3 (bits 15..12) + wires 8..15 (bits 7..0), real, natural space.
//      Tile {bits 15..12, 7..0}; block fixes bits 11..8 = jb. in(f32) -> bufA(half). ----
__global__ void __launch_bounds__(256) k1(const float* __restrict__ in) {
    __shared__ float tile[4096];
    __half* out = (__half*)(void*)g_bufA;
    int s = blockIdx.x >> 4, jb = blockIdx.x & 15;
    int sbase = s << 16;
    int t = threadIdx.x;                       // = lo (bits 7..0)
    {
        float v[16];
#pragma unroll
        for (int h = 0; h < 16; h++) v[h] = in[sbase | (h << 12) | (jb << 8) | t];
        bfly4_real(v, 0, 3);                   // bits 12..15 -> wires 3..0
#pragma unroll
        for (int h = 0; h < 16; h++) tile[swz((h << 8) | t)] = v[h];
    }
    __syncthreads();
    // stage: wires 8..11 (lo bits 7..4)
    {
        int h = t >> 4, m = t & 15;
        float w[16];
#pragma unroll
        for (int j = 0; j < 16; j++) w[j] = tile[swz((h << 8) | (j << 4) | m)];
        bfly4_real(w, 0, 11);
#pragma unroll
        for (int j = 0; j < 16; j++) tile[swz((h << 8) | (j << 4) | m)] = w[j];
    }
    __syncthreads();
    // stage: wires 12..15 (lo bits 3..0, natural space) -> half output, 32B runs
    {
        int h = t >> 4, g = t & 15;
        float w[16];
#pragma unroll
        for (int j = 0; j < 16; j++) w[j] = tile[swz((h << 8) | (g << 4) | j)];
        bfly4_real(w, 0, 15);
        u32 o8[8];
#pragma unroll
        for (int m2 = 0; m2 < 8; m2++) o8[m2] = f2h2(w[2 * m2], w[2 * m2 + 1]);
        uint4* o = (uint4*)(out + (sbase | (h << 12) | (jb << 8) | (g << 4)));
        o[0] = make_uint4(o8[0], o8[1], o8[2], o8[3]);
        o[1] = make_uint4(o8[4], o8[5], o8[6], o8[7]);
    }
}

// ---- K2: L0 wires 4..7 (bits 11..8) + D0 + T0-scatter + L1 wires {4..7, 8..11, 12..14}.
//      dest[15:12]=sfx4(hb) block-fixed; dest[11:0] dense in-tile.
//      bufA(half real) -> bufB (half2, T0-space). ----
__global__ void __launch_bounds__(256) k2() {
    __shared__ u64 st[4096];
    __shared__ float2 sDh[16];
    const __half* in = (const __half*)(const void*)g_bufA;
    u32* out = (u32*)(void*)g_bufB;
    int s = blockIdx.x >> 4, hb = blockIdx.x & 15;     // hb = bits 15..12
    int sbase = s << 16;
    int t = threadIdx.x;                               // bits 7..0
    if (t < 16) sDh[t] = g_Dhi[0][(hb << 4) | t];      // dh for j = t
    float2 dlo = g_Dlo[0][t];
    float v[16];
#pragma unroll
    for (int j = 0; j < 16; j++) v[j] = __half2float(in[sbase | (hb << 12) | (j << 8) | t]);
    bfly4_real(v, 0, 7);                       // bits 8..11 -> wires 7..4
    __syncthreads();                           // sDh visible; st untouched yet
#pragma unroll
    for (int j = 0; j < 16; j++) {
        int a = (hb << 12) | (j << 8) | t;
        int dest = permT(a);                   // dest[15:12] = sfx4(hb), block-fixed
        float2 dh = sDh[j];
        float dcr = dh.x * dlo.x - dh.y * dlo.y;
        float dci = dh.x * dlo.y + dh.y * dlo.x;
        st[sw2(dest & 4095)] = mul2(pk(v[j], v[j]), pk(dcr, dci));
    }
    __syncthreads();
    // stage 1: L1 wires 4..7 (u bits 11..8; stored-bit==true-bit for bits>=1)
    {
        u64 w[16];
#pragma unroll
        for (int j = 0; j < 16; j++) w[j] = st[sw2((j << 8) | t)];
        bfly4_pk(w, 1, 7);
#pragma unroll
        for (int j = 0; j < 16; j++) st[sw2((j << 8) | t)] = w[j];
    }
    __syncthreads();
    // stage 2: L1 wires 8..11 (u bits 7..4)
    {
        int k = t >> 4, m = t & 15;
        u64 w[16];
#pragma unroll
        for (int j = 0; j < 16; j++) w[j] = st[sw2((k << 8) | (j << 4) | m)];
        bfly4_pk(w, 1, 11);
#pragma unroll
        for (int j = 0; j < 16; j++) st[sw2((k << 8) | (j << 4) | m)] = w[j];
    }
    __syncthreads();
    // stage 3: L1 wires 12..14 ONLY (u bits 3..1; bit0=wire15 deferred) + half2 writeout
    {
        int k = t >> 4, g = t & 15;
        u64 w[16];
#pragma unroll
        for (int j = 0; j < 16; j++) w[j] = st[sw2((k << 8) | (g << 4) | j)];
        bfly3_pk(w, 1);
        u32 o16[16];
#pragma unroll
        for (int j = 0; j < 16; j++) o16[j] = h2_from_pk(w[j]);
        int dhi = sfx4(hb);
        uint4* o = (uint4*)(out + (sbase | (dhi << 12) | (k << 8) | (g << 4)));
#pragma unroll
        for (int m2 = 0; m2 < 4; m2++)
            o[m2] = make_uint4(o16[4 * m2], o16[4 * m2 + 1], o16[4 * m2 + 2], o16[4 * m2 + 3]);
    }
}

// ---- K3: relabel gather (T0 -> true) + L1 wire15 (shuffle) + L1 wires 0..3 + D1 +
//      T1-scatter + L2 wires {8..11, 12..14}. bufB(half2) -> bufA(half2, T1-space). ----
__global__ void __launch_bounds__(256) k3() {
    __shared__ u64 st[4096];
    __shared__ float2 sDh[16];
    const u32* in = (const u32*)(const void*)g_bufB;
    u32* out = (u32*)(void*)g_bufA;
    int s = blockIdx.x >> 4, mid = blockIdx.x & 15;
    int lo = threadIdx.x;
    int sbase = s << 16;
    int abase = (mid << 8) | lo;
    if (lo < 16) sDh[lo] = g_Dhi[1][(lo << 4) | mid];
    int hx = (lo & 1) << 3;                    // deferred-parity relabel: flips bit15
    u64 v[16];
#pragma unroll
    for (int h = 0; h < 16; h++) v[h ^ hx] = pk_from_h2(in[sbase | (h << 12) | abase]);
    // v[g] now holds TRUE state (g<<12)|abase.
    {   // L1 wire 15 (true bit 0 = lo&1): partner is lane^1, same register index.
        float2 c15 = g_cs[1][15];
        int odd = lo & 1;
#pragma unroll
        for (int g = 0; g < 16; g++) v[g] = w15_bfly(v[g], c15.x, c15.y, odd);
    }
    bfly4_pk(v, 1, 3);                         // L1 wires 3..0 (bits 15..12)
    float2 dlo = g_Dlo[1][lo];
    __syncthreads();
#pragma unroll
    for (int h = 0; h < 16; h++) {
        int a = (h << 12) | abase;
        int dest = permT(a);                   // T-only: rows dest[15:12]=sfx4(h)
        float2 dh = sDh[h];
        float dcr = dh.x * dlo.x - dh.y * dlo.y;
        float dci = dh.x * dlo.y + dh.y * dlo.x;
        float xr, xi; upk(v[h], xr, xi);
        u64 res = fma2(pk(xi, xi), pk(-dci, dcr), mul2(pk(xr, xr), pk(dcr, dci)));
        st[sw2(((dest >> 12) << 8) | (dest & 255))] = res;
    }
    __syncthreads();
    // stage S: L2 wires 8..11 (dest bits 7..4)
    {
        int k = threadIdx.x >> 4, m = threadIdx.x & 15;
        u64 w[16];
#pragma unroll
        for (int j = 0; j < 16; j++) w[j] = st[sw2((k << 8) | (j << 4) | m)];
        bfly4_pk(w, 2, 11);
#pragma unroll
        for (int j = 0; j < 16; j++) st[sw2((k << 8) | (j << 4) | m)] = w[j];
    }
    __syncthreads();
    // stage T: L2 wires 12..14 ONLY (dest bits 3..1; wire15 deferred to K4) + writeout
    {
        int k = threadIdx.x >> 4, g = threadIdx.x & 15;
        u64 w[16];
#pragma unroll
        for (int j = 0; j < 16; j++) w[j] = st[sw2((k << 8) | (g << 4) | j)];
        bfly3_pk(w, 2);
        u32 o16[16];
#pragma unroll
        for (int j = 0; j < 16; j++) o16[j] = h2_from_pk(w[j]);
        int ms = sfx4(mid);
        int H = (k << 4) | (ms ^ ((k & 1) ? 15 : 0));  // dest bits 8..15 (row-implied)
        uint4* o = (uint4*)(out + (sbase | (H << 8) | (g << 4)));
#pragma unroll
        for (int m2 = 0; m2 < 4; m2++)
            o[m2] = make_uint4(o16[4 * m2], o16[4 * m2 + 1], o16[4 * m2 + 2], o16[4 * m2 + 3]);
    }
}

// ---- K4: relabel gather (T1 -> true) + L2 wire15 (shuffle) + L2 wires 4..7 +
//      wires 0..3 + fused measurement (D2 skipped; ring via permM in sign lookup).
//      bufA(half2) -> partials. ----
__global__ void __launch_bounds__(256) k4() {
    __shared__ u64 st[4096];
    __shared__ float sGhi[256], sGlo[256];
    const u32* in = (const u32*)(const void*)g_bufA;
    int s = blockIdx.x >> 4, lch = blockIdx.x & 15;
    int loBase = lch << 4;
    int sbase = s << 16;
    int t = threadIdx.x;
    sGhi[t] = g_Ghi[t];
    sGlo[t] = g_Glo[t];
    // load tile (bits 15..8 x 16 lo), applying deferred-parity relabel (flip bit15 <-> HH bit7)
    {
        int l = t & 15, Ho = t >> 4;
        int hx = (l & 1) << 7;                 // thread-fixed
#pragma unroll
        for (int i = 0; i < 16; i++) {
            int HH = Ho + (i << 4);
            st[((HH ^ hx) << 4) | l] = pk_from_h2(in[sbase | (HH << 8) | (loBase + l)]);
        }
    }
    __syncthreads();
    // stage A: L2 wire 15 (shuffle, true bit0 = l&1 -> partner thread t^1)
    //          then wires 4..7 (HH bits 0..3 = global bits 8..11)
    {
        int Hhi = t >> 4, l = t & 15;
        float2 c15 = g_cs[2][15];
        int odd = l & 1;
        u64 w[16];
#pragma unroll
        for (int j = 0; j < 16; j++) w[j] = st[(Hhi << 8) | (j << 4) | l];
#pragma unroll
        for (int j = 0; j < 16; j++) w[j] = w15_bfly(w[j], c15.x, c15.y, odd);
        bfly4_pk(w, 2, 7);
#pragma unroll
        for (int j = 0; j < 16; j++) st[(Hhi << 8) | (j << 4) | l] = w[j];
    }
    __syncthreads();
    // stage B: wires 0..3 (HH bits 4..7 = global bits 12..15) + measurement
    float acc = 0.f;
    {
        int Hlo = t >> 4, l = t & 15;
        u64 w[16];
#pragma unroll
        for (int j = 0; j < 16; j++) w[j] = st[(j << 8) | (Hlo << 4) | l];
        bfly4_pk(w, 2, 3);
        u64 accP = pk(0.f, 0.f);
#pragma unroll
        for (int j = 0; j < 16; j++) {
            int HH = (j << 4) | Hlo;
            int y = permM((HH << 8) | (loBase + l));
            float g = sGhi[(y >> 8) & 255] + sGlo[y & 255];
            accP = fma2(w[j], mul2(w[j], pk(g, g)), accP);
        }
        float ar, ai; upk(accP, ar, ai);
        acc = ar + ai;
    }
#pragma unroll
    for (int o = 16; o; o >>= 1) acc += __shfl_xor_sync(0xFFFFFFFFu, acc, o);
    __shared__ float red[8];
    if ((t & 31) == 0) red[t >> 5] = acc;
    __syncthreads();
    if (t == 0) {
        float tt = 0.f;
#pragma unroll
        for (int i = 0; i < 8; i++) tt += red[i];
        g_partials[blockIdx.x] = tt;
    }
}

__global__ void k_final(const float* __restrict__ head_b, float* __restrict__ out) {
    int s = threadIdx.x;  // 128
    float a = 0.f;
#pragma unroll
    for (int m = 0; m < 16; m++) a += g_partials[(s << 4) + m];
    out[s] = head_b[0] + a;
}

extern "C" void kernel_launch(void* const* d_in, const int* in_sizes, int n_in,
                              void* d_out, int out_size) {
    const float* state  = (const float*)d_in[0];  // (128, 65536)
    const float* params = (const float*)d_in[1];  // (3, 16, 2)
    const float* head_w = (const float*)d_in[2];  // (1, 16)
    const float* head_b = (const float*)d_in[3];  // (1,)
    float* out = (float*)d_out;                   // (128,)
    (void)in_sizes; (void)n_in; (void)out_size;

    k_pre<<<1, 256>>>(params, head_w);
    k1<<<2048, 256>>>(state);  // L0 w0..3 + w8..15                  (f32 -> bufA half)
    k2<<<2048, 256>>>();       // L0 w4..7 +D0+T0+ L1 w4..14         (half -> bufB half2, T0)
    k3<<<2048, 256>>>();       // L1 w15,w0..3 +D1+T1+ L2 w8..14     (bufB -> bufA half2, T1)
    k4<<<2048, 256>>>();       // L2 w15,w4..7,w0..3 + measure       (bufA -> partials)
    k_final<<<1, 128>>>(head_b, out);
}

// round 17
// speedup vs baseline: 1.3506x; 1.0184x over previous
#include <cuda_runtime.h>
#include <cuda_fp16.h>

#define BATCH 128
#define DIM   65536
#define NELEM (BATCH * DIM)

typedef unsigned long long u64;
typedef unsigned int u32;

// ---- scratch / precomputed tables (static device memory; no runtime allocs) ----
static __device__ float2 g_bufA[NELEM];          // 64 MB (used as half / half2 views)
static __device__ float2 g_bufB[NELEM];          // 64 MB (used as half2 view)
static __device__ float  g_partials[BATCH * 16];
static __device__ float2 g_cs[3][16];            // (cos(th/2), sin(th/2)) per layer/wire
static __device__ float2 g_Dhi[3][256];          // diagonal phase, wires 0..7  (bits 15..8)
static __device__ float2 g_Dlo[3][256];          // diagonal phase, wires 8..15 (bits 7..0)
static __device__ float  g_Ghi[256];             // head-weighted Z signs, wires 0..7
static __device__ float  g_Glo[256];             // head-weighted Z signs, wires 8..15

// ---- packed f32x2 helpers (FFMA2 path: PTX-only) ----
__device__ __forceinline__ u64 pk(float x, float y) {
    u64 r; asm("mov.b64 %0,{%1,%2};" : "=l"(r) : "f"(x), "f"(y)); return r;
}
__device__ __forceinline__ void upk(u64 a, float& x, float& y) {
    asm("mov.b64 {%0,%1},%2;" : "=f"(x), "=f"(y) : "l"(a));
}
__device__ __forceinline__ u64 fma2(u64 a, u64 b, u64 c) {
    u64 r; asm("fma.rn.f32x2 %0,%1,%2,%3;" : "=l"(r) : "l"(a), "l"(b), "l"(c)); return r;
}
__device__ __forceinline__ u64 mul2(u64 a, u64 b) {
    u64 r; asm("mul.rn.f32x2 %0,%1,%2;" : "=l"(r) : "l"(a), "l"(b)); return r;
}

// ---- fp16 pack/unpack (storage only; all math stays fp32) ----
__device__ __forceinline__ u32 f2h2(float x, float y) {
    u32 r; asm("cvt.rn.f16x2.f32 %0,%1,%2;" : "=r"(r) : "f"(y), "f"(x)); return r;
}
__device__ __forceinline__ u32 h2_from_pk(u64 a) {
    float x, y; upk(a, x, y); return f2h2(x, y);
}
__device__ __forceinline__ u64 pk_from_h2(u32 u) {
    float lo, hi;
    asm("{.reg .f16 a,b; mov.b32 {a,b},%2; cvt.f32.f16 %0,a; cvt.f32.f16 %1,b;}"
        : "=f"(lo), "=f"(hi) : "r"(u));
    return pk(lo, hi);
}

// swizzles
__device__ __forceinline__ int swz(int i) {      // 3-term: f32 tiles (32-bank clean)
    return i ^ ((i >> 4) & 15) ^ (((i >> 8) & 1) << 4);
}
__device__ __forceinline__ int sw2(int i) {      // 2-term: u64 tiles (16-lane phases)
    return i ^ ((i >> 4) & 15);
}

// Pure suffix-XOR permutation (XOR-linear: permT(x^y)=permT(x)^permT(y)).
__device__ __forceinline__ int permT(int a) {
    a ^= a >> 8; a ^= a >> 4; a ^= a >> 2; a ^= a >> 1;
    return a;
}
__device__ __forceinline__ int sfx4(int m) { m ^= m >> 2; m ^= m >> 1; return m & 15; }
__device__ __forceinline__ int par4(int m) { return sfx4(m) & 1; }

// 4 RY butterflies; local bit q of j <-> wire (wtop - q).
__device__ __forceinline__ void bfly4_real(float v[16], int layer, int wtop) {
#pragma unroll
    for (int q = 0; q < 4; q++) {
        float2 cs = g_cs[layer][wtop - q];
        float c = cs.x, s = cs.y;
#pragma unroll
        for (int j = 0; j < 16; j++) {
            if (!(j & (1 << q))) {
                int j1 = j | (1 << q);
                float x0 = v[j], x1 = v[j1];
                v[j]  = c * x0 - s * x1;
                v[j1] = s * x0 + c * x1;
            }
        }
    }
}

__device__ __forceinline__ void bfly4_pk(u64 v[16], int layer, int wtop) {
#pragma unroll
    for (int q = 0; q < 4; q++) {
        float2 cs = g_cs[layer][wtop - q];
        u64 cc = pk(cs.x, cs.x), sp = pk(cs.y, cs.y), sn = pk(-cs.y, -cs.y);
#pragma unroll
        for (int j = 0; j < 16; j++) {
            if (!(j & (1 << q))) {
                int j1 = j | (1 << q);
                u64 x0 = v[j], x1 = v[j1];
                v[j]  = fma2(sn, x1, mul2(cc, x0));
                v[j1] = fma2(sp, x0, mul2(cc, x1));
            }
        }
    }
}

// 3 butterflies on local bits 1..3 only (wires 14..12); bit0 (wire15) deferred.
__device__ __forceinline__ void bfly3_pk(u64 v[16], int layer) {
#pragma unroll
    for (int q = 1; q < 4; q++) {
        float2 cs = g_cs[layer][15 - q];
        u64 cc = pk(cs.x, cs.x), sp = pk(cs.y, cs.y), sn = pk(-cs.y, -cs.y);
#pragma unroll
        for (int j = 0; j < 16; j++) {
            if (!(j & (1 << q))) {
                int j1 = j | (1 << q);
                u64 x0 = v[j], x1 = v[j1];
                v[j]  = fma2(sn, x1, mul2(cc, x0));
                v[j1] = fma2(sp, x0, mul2(cc, x1));
            }
        }
    }
}

// Wire-15 butterfly in true space via lane^1 shuffle.
__device__ __forceinline__ u64 w15_bfly(u64 x, float c, float s, int odd) {
    u64 px = __shfl_xor_sync(0xFFFFFFFFu, x, 1);
    float coef = odd ? s : -s;
    return fma2(pk(coef, coef), px, mul2(pk(c, c), x));
}

// ---- precompute tables ----
__global__ void k_pre(const float* __restrict__ params, const float* __restrict__ head_w) {
    int t = threadIdx.x;  // 256
    if (t < 48) {
        int d = t >> 4, w = t & 15;
        float th = params[(d * 16 + w) * 2 + 0] * 0.5f;
        g_cs[d][w] = make_float2(cosf(th), sinf(th));
    }
    for (int d = 0; d < 3; d++) {
        float ah = 0.f, al = 0.f;
        for (int w = 0; w < 8; w++) {
            float ph = params[(d * 16 + w) * 2 + 1] * 0.5f;
            ah += ((t >> (7 - w)) & 1) ? -ph : ph;
        }
        for (int w = 8; w < 16; w++) {
            float ph = params[(d * 16 + w) * 2 + 1] * 0.5f;
            al += ((t >> (15 - w)) & 1) ? -ph : ph;
        }
        g_Dhi[d][t] = make_float2(cosf(ah), -sinf(ah));
        g_Dlo[d][t] = make_float2(cosf(al), -sinf(al));
    }
    float gh = 0.f, gl = 0.f;
    for (int w = 0; w < 8; w++)  gh += ((t >> (7 - w)) & 1)  ? -head_w[w] : head_w[w];
    for (int w = 8; w < 16; w++) gl += ((t >> (15 - w)) & 1) ? -head_w[w] : head_w[w];
    g_Ghi[t] = gh;
    g_Glo[t] = gl;
}

// ---- K1: L0 wires 0..3 (bits 15..12) + wires 8..15 (bits 7..0), real.
//      Tile {bits 15..12, 7..0}; block fixes bits 11..8 = jb. in(f32) -> bufA(half). ----
__global__ void __launch_bounds__(256) k1(const float* __restrict__ in) {
    __shared__ float tile[4096];
    __half* out = (__half*)(void*)g_bufA;
    int s = blockIdx.x >> 4, jb = blockIdx.x & 15;
    int sbase = s << 16;
    int t = threadIdx.x;                       // = lo (bits 7..0)
    {
        float v[16];
#pragma unroll
        for (int h = 0; h < 16; h++) v[h] = in[sbase | (h << 12) | (jb << 8) | t];
        bfly4_real(v, 0, 3);                   // bits 12..15 -> wires 3..0
#pragma unroll
        for (int h = 0; h < 16; h++) tile[swz((h << 8) | t)] = v[h];
    }
    __syncthreads();
    {
        int h = t >> 4, m = t & 15;
        float w[16];
#pragma unroll
        for (int j = 0; j < 16; j++) w[j] = tile[swz((h << 8) | (j << 4) | m)];
        bfly4_real(w, 0, 11);                  // wires 8..11 (lo bits 7..4)
#pragma unroll
        for (int j = 0; j < 16; j++) tile[swz((h << 8) | (j << 4) | m)] = w[j];
    }
    __syncthreads();
    {
        int h = t >> 4, g = t & 15;
        float w[16];
#pragma unroll
        for (int j = 0; j < 16; j++) w[j] = tile[swz((h << 8) | (g << 4) | j)];
        bfly4_real(w, 0, 15);                  // wires 12..15 (lo bits 3..0)
        u32 o8[8];
#pragma unroll
        for (int m2 = 0; m2 < 8; m2++) o8[m2] = f2h2(w[2 * m2], w[2 * m2 + 1]);
        uint4* o = (uint4*)(out + (sbase | (h << 12) | (jb << 8) | (g << 4)));
        o[0] = make_uint4(o8[0], o8[1], o8[2], o8[3]);
        o[1] = make_uint4(o8[4], o8[5], o8[6], o8[7]);
    }
}

// ---- K2: L0 wires 4..7 + D0 + T0-scatter + L1 wires {4..7, 8..11, 12..14}.
//      bufA(half real) -> bufB (half2, T0-space). permT linearized. ----
__global__ void __launch_bounds__(256) k2() {
    __shared__ u64 st[4096];
    __shared__ float2 sDh[16];
    const __half* in = (const __half*)(const void*)g_bufA;
    u32* out = (u32*)(void*)g_bufB;
    int s = blockIdx.x >> 4, hb = blockIdx.x & 15;     // hb = bits 15..12
    int sbase = s << 16;
    int t = threadIdx.x;                               // bits 7..0
    if (t < 16) sDh[t] = g_Dhi[0][(hb << 4) | t];      // dh for j = t
    float2 dlo = g_Dlo[0][t];
    // permT linearization: dest&4095 = baseLow ^ [(sfx4(j)<<8)|par(j)*0xFF]
    int baseLow = (par4(hb) ? 0xFFF : 0) ^ permT(t);
    float v[16];
#pragma unroll
    for (int j = 0; j < 16; j++) v[j] = __half2float(in[sbase | (hb << 12) | (j << 8) | t]);
    bfly4_real(v, 0, 7);                       // bits 8..11 -> wires 7..4
    __syncthreads();                           // sDh visible; st untouched yet
#pragma unroll
    for (int j = 0; j < 16; j++) {
        int destLow = baseLow ^ ((sfx4(j) << 8) | (par4(j) ? 0xFF : 0));  // j literal
        float2 dh = sDh[j];
        float dcr = dh.x * dlo.x - dh.y * dlo.y;
        float dci = dh.x * dlo.y + dh.y * dlo.x;
        st[sw2(destLow)] = mul2(pk(v[j], v[j]), pk(dcr, dci));
    }
    __syncthreads();
    // stage 1: L1 wires 4..7 (u bits 11..8)
    {
        u64 w[16];
#pragma unroll
        for (int j = 0; j < 16; j++) w[j] = st[sw2((j << 8) | t)];
        bfly4_pk(w, 1, 7);
#pragma unroll
        for (int j = 0; j < 16; j++) st[sw2((j << 8) | t)] = w[j];
    }
    __syncthreads();
    // stage 2: L1 wires 8..11 (u bits 7..4)
    {
        int k = t >> 4, m = t & 15;
        u64 w[16];
#pragma unroll
        for (int j = 0; j < 16; j++) w[j] = st[sw2((k << 8) | (j << 4) | m)];
        bfly4_pk(w, 1, 11);
#pragma unroll
        for (int j = 0; j < 16; j++) st[sw2((k << 8) | (j << 4) | m)] = w[j];
    }
    __syncthreads();
    // stage 3: L1 wires 12..14 ONLY (bit0=wire15 deferred) + half2 writeout
    {
        int k = t >> 4, g = t & 15;
        u64 w[16];
#pragma unroll
        for (int j = 0; j < 16; j++) w[j] = st[sw2((k << 8) | (g << 4) | j)];
        bfly3_pk(w, 1);
        u32 o16[16];
#pragma unroll
        for (int j = 0; j < 16; j++) o16[j] = h2_from_pk(w[j]);
        int dhi = sfx4(hb);
        uint4* o = (uint4*)(out + (sbase | (dhi << 12) | (k << 8) | (g << 4)));
#pragma unroll
        for (int m2 = 0; m2 < 4; m2++)
            o[m2] = make_uint4(o16[4 * m2], o16[4 * m2 + 1], o16[4 * m2 + 2], o16[4 * m2 + 3]);
    }
}

// ---- K3: relabel gather (T0 -> true) + L1 wire15 (shuffle) + L1 wires 0..3 + D1 +
//      T1-scatter + L2 wires {8..11, 12..14}. bufB(half2) -> bufA(half2, T1-space).
//      permT linearized; occupancy forced to 5 blocks/SM. ----
__global__ void __launch_bounds__(256, 5) k3() {
    __shared__ u64 st[4096];
    __shared__ float2 sDh[16];
    const u32* in = (const u32*)(const void*)g_bufB;
    u32* out = (u32*)(void*)g_bufA;
    int s = blockIdx.x >> 4, mid = blockIdx.x & 15;
    int lo = threadIdx.x;
    int sbase = s << 16;
    int abase = (mid << 8) | lo;
    if (lo < 16) sDh[lo] = g_Dhi[1][(lo << 4) | mid];
    int hx = (lo & 1) << 3;                    // deferred-parity relabel: flips bit15
    // permT linearization: pA = permT(abase) < 4096; row(h)=sfx4(h) literal;
    // slot(h) = (pA&255) ^ par(h)*0xFF.
    int pA255 = permT(abase) & 255;
    u64 v[16];
#pragma unroll
    for (int h = 0; h < 16; h++) v[h ^ hx] = pk_from_h2(in[sbase | (h << 12) | abase]);
    // v[g] now holds TRUE state (g<<12)|abase.
    {   // L1 wire 15 (true bit 0 = lo&1): partner lane^1, same register index.
        float2 c15 = g_cs[1][15];
        int odd = lo & 1;
#pragma unroll
        for (int g = 0; g < 16; g++) v[g] = w15_bfly(v[g], c15.x, c15.y, odd);
    }
    bfly4_pk(v, 1, 3);                         // L1 wires 3..0 (bits 15..12)
    float2 dlo = g_Dlo[1][lo];
    __syncthreads();
#pragma unroll
    for (int h = 0; h < 16; h++) {
        int addr = (sfx4(h) << 8) | (pA255 ^ (par4(h) ? 0xFF : 0));  // h literal
        float2 dh = sDh[h];
        float dcr = dh.x * dlo.x - dh.y * dlo.y;
        float dci = dh.x * dlo.y + dh.y * dlo.x;
        float xr, xi; upk(v[h], xr, xi);
        u64 res = fma2(pk(xi, xi), pk(-dci, dcr), mul2(pk(xr, xr), pk(dcr, dci)));
        st[sw2(addr)] = res;
    }
    __syncthreads();
    // stage S: L2 wires 8..11 (dest bits 7..4)
    {
        int k = threadIdx.x >> 4, m = threadIdx.x & 15;
        u64 w[16];
#pragma unroll
        for (int j = 0; j < 16; j++) w[j] = st[sw2((k << 8) | (j << 4) | m)];
        bfly4_pk(w, 2, 11);
#pragma unroll
        for (int j = 0; j < 16; j++) st[sw2((k << 8) | (j << 4) | m)] = w[j];
    }
    __syncthreads();
    // stage T: L2 wires 12..14 ONLY (wire15 deferred to K4) + writeout
    {
        int k = threadIdx.x >> 4, g = threadIdx.x & 15;
        u64 w[16];
#pragma unroll
        for (int j = 0; j < 16; j++) w[j] = st[sw2((k << 8) | (g << 4) | j)];
        bfly3_pk(w, 2);
        u32 o16[16];
#pragma unroll
        for (int j = 0; j < 16; j++) o16[j] = h2_from_pk(w[j]);
        int ms = sfx4(mid);
        int H = (k << 4) | (ms ^ ((k & 1) ? 15 : 0));  // dest bits 8..15 (row-implied)
        uint4* o = (uint4*)(out + (sbase | (H << 8) | (g << 4)));
#pragma unroll
        for (int m2 = 0; m2 < 4; m2++)
            o[m2] = make_uint4(o16[4 * m2], o16[4 * m2 + 1], o16[4 * m2 + 2], o16[4 * m2 + 3]);
    }
}

// ---- K4: relabel gather (T1 -> true) + L2 wire15 (shuffle) + L2 wires 4..7 +
//      wires 0..3 + fused measurement. permM linearized to 1 XOR + 2-entry Glo.
//      bufA(half2) -> partials. ----
__global__ void __launch_bounds__(256) k4() {
    __shared__ u64 st[4096];
    __shared__ float sGhi[256], sGlo[256];
    const u32* in = (const u32*)(const void*)g_bufA;
    int s = blockIdx.x >> 4, lch = blockIdx.x & 15;
    int loBase = lch << 4;
    int sbase = s << 16;
    int t = threadIdx.x;
    sGhi[t] = g_Ghi[t];
    sGlo[t] = g_Glo[t];
    // load tile (bits 15..8 x 16 lo), deferred-parity relabel (flip bit15 <-> HH bit7)
    {
        int l = t & 15, Ho = t >> 4;
        int hx = (l & 1) << 7;                 // thread-fixed
#pragma unroll
        for (int i = 0; i < 16; i++) {
            int HH = Ho + (i << 4);
            st[((HH ^ hx) << 4) | l] = pk_from_h2(in[sbase | (HH << 8) | (loBase + l)]);
        }
    }
    __syncthreads();
    // stage A: L2 wire 15 (shuffle) then wires 4..7 (HH bits 0..3 = bits 11..8)
    {
        int Hhi = t >> 4, l = t & 15;
        float2 c15 = g_cs[2][15];
        int odd = l & 1;
        u64 w[16];
#pragma unroll
        for (int j = 0; j < 16; j++) w[j] = st[(Hhi << 8) | (j << 4) | l];
#pragma unroll
        for (int j = 0; j < 16; j++) w[j] = w15_bfly(w[j], c15.x, c15.y, odd);
        bfly4_pk(w, 2, 7);
#pragma unroll
        for (int j = 0; j < 16; j++) st[(Hhi << 8) | (j << 4) | l] = w[j];
    }
    __syncthreads();
    // stage B: wires 0..3 (HH bits 4..7 = bits 15..12) + measurement
    float acc = 0.f;
    {
        int Hlo = t >> 4, l = t & 15;
        u64 w[16];
#pragma unroll
        for (int j = 0; j < 16; j++) w[j] = st[(j << 8) | (Hlo << 4) | l];
        bfly4_pk(w, 2, 3);
        // permM linearization: A = (((j<<4)|Hlo)<<8)|lo2, lo2 = loBase+l.
        // y = Lj ^ B with Lj = permT(j<<12) ^ (par(j)<<15) [literal],
        // B = permT(Hlo<<8) ^ permT(lo2) ^ (pb<<15), pb = parity bit of that base.
        int lo2 = loBase + l;
        int base = ((sfx4(Hlo) << 8) | (par4(Hlo) ? 0xFF : 0)) ^ permT(lo2);
        int B = base ^ ((base & 1) << 15);
        float gl0 = sGlo[B & 255], gl1 = sGlo[(B & 255) ^ 0xFF];
        u64 accP = pk(0.f, 0.f);
#pragma unroll
        for (int j = 0; j < 16; j++) {
            int Lj = ((sfx4(j) << 12) | (par4(j) ? 0xFFF : 0)) ^ (par4(j) << 15); // literal
            int y = Lj ^ B;
            float g = sGhi[(y >> 8) & 255] + (par4(j) ? gl1 : gl0);
            accP = fma2(w[j], mul2(w[j], pk(g, g)), accP);
        }
        float ar, ai; upk(accP, ar, ai);
        acc = ar + ai;
    }
#pragma unroll
    for (int o = 16; o; o >>= 1) acc += __shfl_xor_sync(0xFFFFFFFFu, acc, o);
    __shared__ float red[8];
    if ((t & 31) == 0) red[t >> 5] = acc;
    __syncthreads();
    if (t == 0) {
        float tt = 0.f;
#pragma unroll
        for (int i = 0; i < 8; i++) tt += red[i];
        g_partials[blockIdx.x] = tt;
    }
}

__global__ void k_final(const float* __restrict__ head_b, float* __restrict__ out) {
    int s = threadIdx.x;  // 128
    float a = 0.f;
#pragma unroll
    for (int m = 0; m < 16; m++) a += g_partials[(s << 4) + m];
    out[s] = head_b[0] + a;
}

extern "C" void kernel_launch(void* const* d_in, const int* in_sizes, int n_in,
                              void* d_out, int out_size) {
    const float* state  = (const float*)d_in[0];  // (128, 65536)
    const float* params = (const float*)d_in[1];  // (3, 16, 2)
    const float* head_w = (const float*)d_in[2];  // (1, 16)
    const float* head_b = (const float*)d_in[3];  // (1,)
    float* out = (float*)d_out;                   // (128,)
    (void)in_sizes; (void)n_in; (void)out_size;

    k_pre<<<1, 256>>>(params, head_w);
    k1<<<2048, 256>>>(state);  // L0 w0..3 + w8..15                  (f32 -> bufA half)
    k2<<<2048, 256>>>();       // L0 w4..7 +D0+T0+ L1 w4..14         (half -> bufB half2, T0)
    k3<<<2048, 256>>>();       // L1 w15,w0..3 +D1+T1+ L2 w8..14     (bufB -> bufA half2, T1)
    k4<<<2048, 256>>>();       // L2 w15,w4..7,w0..3 + measure       (bufA -> partials)
    k_final<<<1, 128>>>(head_b, out);
}